// round 2
// baseline (speedup 1.0000x reference)
#include <cuda_runtime.h>
#include <cuda_bf16.h>

#define BB 8
#define LL 4096
#define HH 512
#define NN 16
#define NLAYERS 4

// ---------------- scratch (static device globals; no runtime alloc) ----------
__device__ float g_h [BB*LL*HH];            // residual stream, (B,L,H)
__device__ float g_ut[(size_t)BB*HH*LL];    // LN output, transposed (B,H,L)
__device__ float g_yt[(size_t)BB*HH*LL];    // gelu(conv out), transposed (B,H,L)
__device__ float g_w [NLAYERS*HH*NN*2];     // discrete poles w = exp(dt*A), complex
__device__ float g_ct[NLAYERS*2*HH*NN*2];   // 2 * C * (exp(dt*A)-1)/A, complex

// ---------------- SSM parameter precompute ----------------------------------
__global__ void k_params(const float* __restrict__ log_dt, const float* __restrict__ A_re,
                         const float* __restrict__ A_im, const float* __restrict__ C_re,
                         const float* __restrict__ C_im) {
    int idx = blockIdx.x * blockDim.x + threadIdx.x;
    if (idx >= NLAYERS*HH*NN) return;
    int n     = idx % NN;
    int h     = (idx / NN) % HH;
    int layer = idx / (HH*NN);
    float dt  = expf(log_dt[layer*HH + h]);
    float are = A_re[idx];
    float aim = A_im[idx];
    float dre = are*dt, dim = aim*dt;
    float e   = expf(dre);
    float wre = e * cosf(dim);
    float wim = e * sinf(dim);
    g_w[idx*2+0] = wre;
    g_w[idx*2+1] = wim;
    // f = (w - 1) / A
    float inv = 1.0f / (are*are + aim*aim);
    float nre = wre - 1.0f, nim = wim;
    float fre = (nre*are + nim*aim) * inv;
    float fim = (nim*are - nre*aim) * inv;
    #pragma unroll
    for (int c = 0; c < 2; c++) {
        int cidx = ((layer*2 + c)*HH + h)*NN + n;
        float cre = C_re[cidx], cim = C_im[cidx];
        g_ct[cidx*2+0] = 2.0f*(cre*fre - cim*fim);   // fold 2*Re(.) into C
        g_ct[cidx*2+1] = 2.0f*(cre*fim + cim*fre);
    }
}

// ---------------- encoder ----------------------------------------------------
__global__ void k_encoder(const float* __restrict__ x, const float* __restrict__ enc_w,
                          const float* __restrict__ enc_b) {
    int idx = blockIdx.x * blockDim.x + threadIdx.x;   // exact grid over B*L*H
    int hh = idx % HH;
    int l  = (idx / HH) % LL;
    int b  = idx / (LL*HH);
    float grid = (float)l * (1.0f/(LL-1));
    g_h[idx] = enc_w[hh*2+0]*x[b*LL + l] + enc_w[hh*2+1]*grid + enc_b[hh];
}

// ---------------- LayerNorm + transpose to (B,H,L) ---------------------------
__global__ void __launch_bounds__(256) k_ln_t(const float* __restrict__ ln_w,
                                              const float* __restrict__ ln_b, int layer) {
    __shared__ float s_mean[32], s_rstd[32];
    __shared__ float tile[64][33];
    int b  = blockIdx.y;
    int l0 = blockIdx.x * 32;
    int tid = threadIdx.x, warp = tid >> 5, lane = tid & 31;
    const float* lw = ln_w + layer*HH;
    const float* lb = ln_b + layer*HH;

    for (int r = warp; r < 32; r += 8) {
        const float* row = g_h + ((size_t)b*LL + l0 + r)*HH;
        float sum = 0.f, sq = 0.f;
        #pragma unroll
        for (int j = 0; j < 16; j++) { float v = row[lane + 32*j]; sum += v; sq += v*v; }
        #pragma unroll
        for (int o = 16; o > 0; o >>= 1) {
            sum += __shfl_xor_sync(0xffffffffu, sum, o);
            sq  += __shfl_xor_sync(0xffffffffu, sq , o);
        }
        if (lane == 0) {
            float mu = sum * (1.0f/HH);
            s_mean[r] = mu;
            s_rstd[r] = rsqrtf(sq * (1.0f/HH) - mu*mu + 1e-5f);
        }
    }
    __syncthreads();

    for (int h0 = 0; h0 < HH; h0 += 64) {
        #pragma unroll
        for (int p = 0; p < 8; p++) {
            int r = p*4 + (tid >> 6);
            int c = tid & 63;
            float v = g_h[((size_t)b*LL + l0 + r)*HH + h0 + c];
            tile[c][r] = (v - s_mean[r]) * s_rstd[r] * lw[h0 + c] + lb[h0 + c];
        }
        __syncthreads();
        #pragma unroll
        for (int p = 0; p < 8; p++) {
            int hh = p*8 + (tid >> 5);
            int lc = tid & 31;
            g_ut[((size_t)b*HH + h0 + hh)*LL + l0 + lc] = tile[hh][lc];
        }
        __syncthreads();
    }
}

// ---------------- bidirectional diagonal-SSM scan + D*u + exact GELU ---------
// One block per (b,h). 256 threads = 16 chunks x 2 dirs x 8 n-threads (2 n each).
__global__ void __launch_bounds__(256) k_scan(const float* __restrict__ Din, int layer) {
    __shared__ float su[4113];              // skewed u, plus u[4096]=0 pad
    __shared__ float st[2*16*16*2];         // chunk-local sums  [dir][chunk][n]{re,im}
    __shared__ float carr[2*16*16*2];       // carry into chunk  [dir][chunk][n]{re,im}
    __shared__ float sy[4096];

    int bh = blockIdx.x;
    int h  = bh & 511;
    int tid = threadIdx.x;
    const float* urow = g_ut + (size_t)bh * LL;

    for (int t = tid; t < 4096; t += 256) su[t + (t >> 8)] = urow[t];
    if (tid == 0) su[4112] = 0.0f;          // u[4096] = 0
    __syncthreads();

    float Dh = Din[layer*HH + h];
    for (int t = tid; t < 4096; t += 256) sy[t] = Dh * su[t + (t >> 8)];

    int n8    = tid & 7;                    // owns n8 and n8+8
    int dir   = (tid >> 3) & 1;             // 0 = forward, 1 = backward
    int chunk = tid >> 4;                   // 0..15
    int t0    = chunk << 8;

    const float* wb = g_w  + (size_t)(layer*HH + h)*NN*2;
    const float* cb = g_ct + (size_t)((layer*2 + dir)*HH + h)*NN*2;
    float w_re[2], w_im[2], c_re[2], c_im[2];
    #pragma unroll
    for (int k = 0; k < 2; k++) {
        int n = n8 + 8*k;
        w_re[k] = wb[n*2]; w_im[k] = wb[n*2+1];
        c_re[k] = cb[n*2]; c_im[k] = cb[n*2+1];
    }

    // pass 1: chunk-local sums from zero state
    float a_re[2] = {0.f, 0.f}, a_im[2] = {0.f, 0.f};
    #pragma unroll 4
    for (int i = 0; i < 256; i++) {
        int t = dir ? (t0 + 256 - i) : (t0 + i);
        float u = su[t + (t >> 8)];
        #pragma unroll
        for (int k = 0; k < 2; k++) {
            float tre = fmaf(w_re[k], a_re[k], u);
            float tim = fmaf(w_re[k], a_im[k], w_im[k]*a_re[k]);
            a_re[k] = fmaf(-w_im[k], a_im[k], tre);
            a_im[k] = tim;
        }
    }
    #pragma unroll
    for (int k = 0; k < 2; k++) {
        int sidx = ((dir*16 + chunk)*16 + n8 + 8*k)*2;
        st[sidx+0] = a_re[k];
        st[sidx+1] = a_im[k];
    }
    __syncthreads();

    // combine: serial carry propagation across 16 chunks (32 threads: dir x n)
    if (tid < 32) {
        int n = tid & 15, d = tid >> 4;
        float wre = wb[n*2], wim = wb[n*2+1];
        float pre = wre, pim = wim;                    // w^256 via 8 squarings
        #pragma unroll
        for (int q = 0; q < 8; q++) {
            float nr = pre*pre - pim*pim;
            float ni = 2.0f*pre*pim;
            pre = nr; pim = ni;
        }
        float Fre = 0.f, Fim = 0.f;
        if (d == 0) {
            for (int c = 0; c < 16; c++) {
                int ci = (c*16 + n)*2;
                carr[ci] = Fre; carr[ci+1] = Fim;      // state entering chunk c
                float sre = st[ci], sim = st[ci+1];
                float nr = pre*Fre - pim*Fim + sre;
                float ni = pre*Fim + pim*Fre + sim;
                Fre = nr; Fim = ni;
            }
        } else {
            for (int c = 15; c >= 0; c--) {
                int ci = ((16 + c)*16 + n)*2;
                carr[ci] = Fre; carr[ci+1] = Fim;      // state entering from the right
                float sre = st[ci], sim = st[ci+1];
                float nr = pre*Fre - pim*Fim + sre;
                float ni = pre*Fim + pim*Fre + sim;
                Fre = nr; Fim = ni;
            }
        }
    }
    __syncthreads();

    // pass 2: full scan with carries; both dirs are update(u) -> emit
    float s_re[2], s_im[2];
    #pragma unroll
    for (int k = 0; k < 2; k++) {
        int ci = ((dir*16 + chunk)*16 + n8 + 8*k)*2;
        s_re[k] = carr[ci]; s_im[k] = carr[ci+1];
    }
    #pragma unroll 4
    for (int i = 0; i < 256; i++) {
        int tout = dir ? (t0 + 255 - i) : (t0 + i);
        int tu   = tout + dir;                          // bwd consumes u[t+1]
        float u  = su[tu + (tu >> 8)];
        float v  = 0.f;
        #pragma unroll
        for (int k = 0; k < 2; k++) {
            float tre = fmaf(w_re[k], s_re[k], u);
            float tim = fmaf(w_re[k], s_im[k], w_im[k]*s_re[k]);
            s_re[k] = fmaf(-w_im[k], s_im[k], tre);
            s_im[k] = tim;
            v = fmaf(c_re[k], s_re[k], v);
            v = fmaf(-c_im[k], s_im[k], v);
        }
        v += __shfl_xor_sync(0xffffffffu, v, 1);
        v += __shfl_xor_sync(0xffffffffu, v, 2);
        v += __shfl_xor_sync(0xffffffffu, v, 4);
        if ((tid & 7) == 0) sy[tout] += v;  // fwd/bwd same chunk share a warp: ordered
    }
    __syncthreads();

    // epilogue: exact-erf GELU, write (B,H,L)
    float* orow = g_yt + (size_t)bh * LL;
    for (int t = tid; t < 4096; t += 256) {
        float v = sy[t];
        orow[t] = 0.5f * v * (1.0f + erff(v * 0.70710678118f));
    }
}

// ---------------- output linear + GLU + residual -----------------------------
// z0 = y@W[0:H].T, z1 = y@W[H:2H].T ; h += (z0+b0) * sigmoid(z1+b1)
__global__ void __launch_bounds__(256) k_gemm_glu(const float* __restrict__ out_w,
                                                  const float* __restrict__ out_b, int layer) {
    __shared__ float As [16][68];
    __shared__ float Bs0[16][68];
    __shared__ float Bs1[16][68];
    int tid = threadIdx.x;
    int n0  = blockIdx.x * 64;            // column tile within [0,512)
    int m0  = blockIdx.y * 64;            // row tile over B*L
    int b   = m0 >> 12;
    int l0  = m0 & 4095;
    const float* W    = out_w + (size_t)layer*2*HH*HH;
    const float* bias = out_b + (size_t)layer*2*HH;
    const float* Ab   = g_yt  + (size_t)b*HH*LL;

    float acc0[4][4] = {}, acc1[4][4] = {};
    int tx = tid & 15, ty = tid >> 4;
    int am = tid & 63, ak = tid >> 6;          // A loader: 64 m x 4 k-groups
    int bk = tid & 15, bn = tid >> 4;          // B loader: 16 k x 16 n-groups

    for (int kk = 0; kk < HH; kk += 16) {
        #pragma unroll
        for (int j = 0; j < 4; j++) {
            int k = ak*4 + j;
            As[k][am] = Ab[(size_t)(kk + k)*LL + l0 + am];
        }
        #pragma unroll
        for (int j = 0; j < 4; j++) {
            int nn = bn + 16*j;
            Bs0[bk][nn] = W[(size_t)(n0 + nn)*HH + kk + bk];
            Bs1[bk][nn] = W[(size_t)(HH + n0 + nn)*HH + kk + bk];
        }
        __syncthreads();
        #pragma unroll
        for (int k = 0; k < 16; k++) {
            float4 a  = *(const float4*)&As [k][tx*4];
            float4 b0 = *(const float4*)&Bs0[k][ty*4];
            float4 b1 = *(const float4*)&Bs1[k][ty*4];
            float av[4] = {a.x, a.y, a.z, a.w};
            float b0v[4] = {b0.x, b0.y, b0.z, b0.w};
            float b1v[4] = {b1.x, b1.y, b1.z, b1.w};
            #pragma unroll
            for (int i = 0; i < 4; i++)
                #pragma unroll
                for (int j = 0; j < 4; j++) {
                    acc0[i][j] = fmaf(av[i], b0v[j], acc0[i][j]);
                    acc1[i][j] = fmaf(av[i], b1v[j], acc1[i][j]);
                }
        }
        __syncthreads();
    }

    #pragma unroll
    for (int j = 0; j < 4; j++) {
        int n = n0 + ty*4 + j;
        float b0 = bias[n], b1 = bias[HH + n];
        #pragma unroll
        for (int i = 0; i < 4; i++) {
            int m = m0 + tx*4 + i;
            float z0 = acc0[i][j] + b0;
            float z1 = acc1[i][j] + b1;
            float g  = z0 / (1.0f + expf(-z1));
            g_h[(size_t)m*HH + n] += g;
        }
    }
}

// ---------------- decoder -----------------------------------------------------
__global__ void __launch_bounds__(256) k_decoder(const float* __restrict__ dec_w,
                                                 const float* __restrict__ dec_b,
                                                 float* __restrict__ out) {
    int row  = blockIdx.x*8 + (threadIdx.x >> 5);
    int lane = threadIdx.x & 31;
    const float* hr = g_h + (size_t)row*HH;
    float s = 0.f;
    #pragma unroll
    for (int j = 0; j < 16; j++) s = fmaf(hr[lane + 32*j], dec_w[lane + 32*j], s);
    #pragma unroll
    for (int o = 16; o > 0; o >>= 1) s += __shfl_xor_sync(0xffffffffu, s, o);
    if (lane == 0) out[row] = s + dec_b[0];
}

// ---------------- driver ------------------------------------------------------
extern "C" void kernel_launch(void* const* d_in, const int* in_sizes, int n_in,
                              void* d_out, int out_size) {
    const float* x      = (const float*)d_in[0];
    const float* enc_w  = (const float*)d_in[1];
    const float* enc_b  = (const float*)d_in[2];
    const float* log_dt = (const float*)d_in[3];
    const float* A_re   = (const float*)d_in[4];
    const float* A_im   = (const float*)d_in[5];
    const float* C_re   = (const float*)d_in[6];
    const float* C_im   = (const float*)d_in[7];
    const float* D      = (const float*)d_in[8];
    const float* out_w  = (const float*)d_in[9];
    const float* out_b  = (const float*)d_in[10];
    const float* ln_w   = (const float*)d_in[11];
    const float* ln_b   = (const float*)d_in[12];
    const float* dec_w  = (const float*)d_in[13];
    const float* dec_b  = (const float*)d_in[14];
    float* out = (float*)d_out;

    k_params<<<(NLAYERS*HH*NN + 255)/256, 256>>>(log_dt, A_re, A_im, C_re, C_im);
    k_encoder<<<(BB*LL*HH)/256, 256>>>(x, enc_w, enc_b);

    for (int layer = 0; layer < NLAYERS; layer++) {
        dim3 lgrid(LL/32, BB);
        k_ln_t<<<lgrid, 256>>>(ln_w, ln_b, layer);
        k_scan<<<BB*HH, 256>>>(D, layer);
        dim3 ggrid(HH/64, (BB*LL)/64);
        k_gemm_glu<<<ggrid, 256>>>(out_w, out_b, layer);
    }
    k_decoder<<<(BB*LL)/8, 256>>>(dec_w, dec_b, out);
}

// round 3
// speedup vs baseline: 1.0572x; 1.0572x over previous
#include <cuda_runtime.h>
#include <cuda_bf16.h>

#define BB 8
#define LL 4096
#define HH 512
#define NN 16
#define NLAYERS 4

typedef unsigned long long u64;

__device__ __forceinline__ u64 pk2(float lo, float hi) {
    u64 r; asm("mov.b64 %0,{%1,%2};" : "=l"(r) : "f"(lo), "f"(hi)); return r;
}
__device__ __forceinline__ void upk2(u64 v, float& lo, float& hi) {
    asm("mov.b64 {%0,%1},%2;" : "=f"(lo), "=f"(hi) : "l"(v));
}
__device__ __forceinline__ u64 f2fma(u64 a, u64 b, u64 c) {
    u64 d; asm("fma.rn.f32x2 %0,%1,%2,%3;" : "=l"(d) : "l"(a), "l"(b), "l"(c)); return d;
}

// ---------------- scratch ----------------------------------------------------
__device__ float g_h [BB*LL*HH];            // residual stream, (B,L,H)
__device__ float g_ut[(size_t)BB*HH*LL];    // LN output, transposed (B,H,L)
__device__ float g_yt[(size_t)BB*HH*LL];    // gelu(conv out), transposed (B,H,L)
__device__ float g_w [NLAYERS*HH*NN*2];     // discrete poles w = exp(dt*A)
__device__ float g_ct[NLAYERS*2*HH*NN*2];   // 2 * C * (exp(dt*A)-1)/A

// ---------------- SSM parameter precompute ----------------------------------
__global__ void k_params(const float* __restrict__ log_dt, const float* __restrict__ A_re,
                         const float* __restrict__ A_im, const float* __restrict__ C_re,
                         const float* __restrict__ C_im) {
    int idx = blockIdx.x * blockDim.x + threadIdx.x;
    if (idx >= NLAYERS*HH*NN) return;
    int n     = idx % NN;
    int h     = (idx / NN) % HH;
    int layer = idx / (HH*NN);
    float dt  = expf(log_dt[layer*HH + h]);
    float are = A_re[idx];
    float aim = A_im[idx];
    float e   = expf(are*dt);
    float wre = e * cosf(aim*dt);
    float wim = e * sinf(aim*dt);
    g_w[idx*2+0] = wre;
    g_w[idx*2+1] = wim;
    float inv = 1.0f / (are*are + aim*aim);
    float nre = wre - 1.0f, nim = wim;
    float fre = (nre*are + nim*aim) * inv;
    float fim = (nim*are - nre*aim) * inv;
    #pragma unroll
    for (int c = 0; c < 2; c++) {
        int cidx = ((layer*2 + c)*HH + h)*NN + n;
        float cre = C_re[cidx], cim = C_im[cidx];
        g_ct[cidx*2+0] = 2.0f*(cre*fre - cim*fim);
        g_ct[cidx*2+1] = 2.0f*(cre*fim + cim*fre);
    }
}

// ---------------- encoder ----------------------------------------------------
__global__ void k_encoder(const float* __restrict__ x, const float* __restrict__ enc_w,
                          const float* __restrict__ enc_b) {
    int idx = blockIdx.x * blockDim.x + threadIdx.x;
    int hh = idx % HH;
    int l  = (idx / HH) % LL;
    int b  = idx / (LL*HH);
    float grid = (float)l * (1.0f/(LL-1));
    g_h[idx] = enc_w[hh*2+0]*x[b*LL + l] + enc_w[hh*2+1]*grid + enc_b[hh];
}

// ---------------- LayerNorm + transpose to (B,H,L) ---------------------------
__global__ void __launch_bounds__(256) k_ln_t(const float* __restrict__ ln_w,
                                              const float* __restrict__ ln_b, int layer) {
    __shared__ float s_mean[32], s_rstd[32];
    __shared__ float tile[64][33];
    int b  = blockIdx.y;
    int l0 = blockIdx.x * 32;
    int tid = threadIdx.x, warp = tid >> 5, lane = tid & 31;
    const float* lw = ln_w + layer*HH;
    const float* lb = ln_b + layer*HH;

    for (int r = warp; r < 32; r += 8) {
        const float* row = g_h + ((size_t)b*LL + l0 + r)*HH;
        float sum = 0.f, sq = 0.f;
        #pragma unroll
        for (int j = 0; j < 16; j++) { float v = row[lane + 32*j]; sum += v; sq += v*v; }
        #pragma unroll
        for (int o = 16; o > 0; o >>= 1) {
            sum += __shfl_xor_sync(0xffffffffu, sum, o);
            sq  += __shfl_xor_sync(0xffffffffu, sq , o);
        }
        if (lane == 0) {
            float mu = sum * (1.0f/HH);
            s_mean[r] = mu;
            s_rstd[r] = rsqrtf(sq * (1.0f/HH) - mu*mu + 1e-5f);
        }
    }
    __syncthreads();

    for (int h0 = 0; h0 < HH; h0 += 64) {
        #pragma unroll
        for (int p = 0; p < 8; p++) {
            int r = p*4 + (tid >> 6);
            int c = tid & 63;
            float v = g_h[((size_t)b*LL + l0 + r)*HH + h0 + c];
            tile[c][r] = (v - s_mean[r]) * s_rstd[r] * lw[h0 + c] + lb[h0 + c];
        }
        __syncthreads();
        #pragma unroll
        for (int p = 0; p < 8; p++) {
            int hh = p*8 + (tid >> 5);
            int lc = tid & 31;
            g_ut[((size_t)b*HH + h0 + hh)*LL + l0 + lc] = tile[hh][lc];
        }
        __syncthreads();
    }
}

// ---------------- bidirectional diagonal-SSM scan + D*u + exact GELU ---------
// One block per (b,h). 256 threads = 32 chunks(128 steps) x 2 dirs x 4 n-threads.
__global__ void __launch_bounds__(256) k_scan(const float* __restrict__ Din, int layer) {
    __shared__ float su[4129];       // skewed: idx = t + (t>>7); su[4128] = 0 pad
    __shared__ float sy[4129];       // skewed output accumulator
    __shared__ u64 st64[2*32*16];    // chunk-local sums  [dir][chunk][n]
    __shared__ u64 carr64[2*32*16];  // carry into chunk  [dir][chunk][n]

    int bh = blockIdx.x;
    int h  = bh & 511;
    int tid = threadIdx.x;
    const float* urow = g_ut + (size_t)bh * LL;

    for (int t = tid; t < 4096; t += 256) su[t + (t >> 7)] = urow[t];
    if (tid == 0) su[4128] = 0.0f;
    __syncthreads();

    float Dh = Din[layer*HH + h];
    for (int t = tid; t < 4096; t += 256) {
        int ts = t + (t >> 7);
        sy[ts] = Dh * su[ts];
    }

    int n4    = tid & 3;                    // owns n = n4 + 4*k, k=0..3
    int dir   = (tid >> 2) & 1;             // 0 = forward, 1 = backward
    int chunk = tid >> 3;                   // 0..31
    int t0    = chunk << 7;

    const float* wb = g_w  + (size_t)(layer*HH + h)*NN*2;
    const float* cb = g_ct + (size_t)((layer*2 + dir)*HH + h)*NN*2;
    u64 wr2[4], wi2[4], cc[4];
    #pragma unroll
    for (int k = 0; k < 4; k++) {
        int n = n4 + 4*k;
        float wre = wb[n*2], wim = wb[n*2+1];
        float cre = cb[n*2], cim = cb[n*2+1];
        wr2[k] = pk2(wre, wre);
        wi2[k] = pk2(-wim, wim);
        cc[k]  = pk2(cre, -cim);
    }

    // pass 1: chunk-local sums from zero state
    u64 s[4] = {0ULL, 0ULL, 0ULL, 0ULL};
    #pragma unroll 4
    for (int i = 0; i < 128; i++) {
        int t = dir ? (t0 + 128 - i) : (t0 + i);
        float u = su[t + (t >> 7)];
        u64 u2 = pk2(u, 0.0f);
        #pragma unroll
        for (int k = 0; k < 4; k++) {
            float slo, shi; upk2(s[k], slo, shi);
            u64 sw = pk2(shi, slo);
            s[k] = f2fma(wi2[k], sw, f2fma(wr2[k], s[k], u2));
        }
    }
    #pragma unroll
    for (int k = 0; k < 4; k++)
        st64[(dir*32 + chunk)*16 + n4 + 4*k] = s[k];
    __syncthreads();

    // combine: serial carry propagation across 32 chunks (32 threads: dir x n)
    if (tid < 32) {
        int n = tid & 15, d = tid >> 4;
        float wre = wb[n*2], wim = wb[n*2+1];
        float pre = wre, pim = wim;            // w^128 via 7 squarings
        #pragma unroll
        for (int q = 0; q < 7; q++) {
            float nr = pre*pre - pim*pim;
            float ni = 2.0f*pre*pim;
            pre = nr; pim = ni;
        }
        float Fre = 0.f, Fim = 0.f;
        if (d == 0) {
            for (int c = 0; c < 32; c++) {
                int sl = c*16 + n;
                carr64[sl] = pk2(Fre, Fim);
                float sre, sim; upk2(st64[sl], sre, sim);
                float nr = pre*Fre - pim*Fim + sre;
                float ni = pre*Fim + pim*Fre + sim;
                Fre = nr; Fim = ni;
            }
        } else {
            for (int c = 31; c >= 0; c--) {
                int sl = (32 + c)*16 + n;
                carr64[sl] = pk2(Fre, Fim);
                float sre, sim; upk2(st64[sl], sre, sim);
                float nr = pre*Fre - pim*Fim + sre;
                float ni = pre*Fim + pim*Fre + sim;
                Fre = nr; Fim = ni;
            }
        }
    }
    __syncthreads();

    // pass 2: full scan with carries; emit per timestep
    #pragma unroll
    for (int k = 0; k < 4; k++)
        s[k] = carr64[(dir*32 + chunk)*16 + n4 + 4*k];
    #pragma unroll 4
    for (int i = 0; i < 128; i++) {
        int tout = dir ? (t0 + 127 - i) : (t0 + i);
        int tu   = tout + dir;                  // bwd consumes u[t+1]
        float u  = su[tu + (tu >> 7)];
        u64 u2   = pk2(u, 0.0f);
        u64 v2   = 0ULL;
        #pragma unroll
        for (int k = 0; k < 4; k++) {
            float slo, shi; upk2(s[k], slo, shi);
            u64 sw = pk2(shi, slo);
            s[k] = f2fma(wi2[k], sw, f2fma(wr2[k], s[k], u2));
            v2 = f2fma(cc[k], s[k], v2);
        }
        float va, vb; upk2(v2, va, vb);
        float v = va + vb;
        v += __shfl_xor_sync(0xffffffffu, v, 1);
        v += __shfl_xor_sync(0xffffffffu, v, 2);
        if (n4 == 0) sy[tout + (tout >> 7)] += v;   // fwd/bwd addrs never collide
    }
    __syncthreads();

    // epilogue: exact-erf GELU, write (B,H,L)
    float* orow = g_yt + (size_t)bh * LL;
    for (int t = tid; t < 4096; t += 256) {
        float v = sy[t + (t >> 7)];
        orow[t] = 0.5f * v * (1.0f + erff(v * 0.70710678118f));
    }
}

// ---------------- output linear + GLU + residual (f32x2 packed) --------------
// 128x64 block tile, 8x4 per thread. z0=y@W0.T, z1=y@W1.T; h += (z0+b0)*sig(z1+b1)
__global__ void __launch_bounds__(256) k_gemm_glu(const float* __restrict__ out_w,
                                                  const float* __restrict__ out_b, int layer) {
    __shared__ float As [16][136];
    __shared__ float Bs0[16][68];
    __shared__ float Bs1[16][68];
    int tid = threadIdx.x;
    int n0  = blockIdx.x * 64;             // column tile within [0,512)
    int m0  = blockIdx.y * 128;            // row tile over B*L
    int b   = m0 >> 12;
    int l0  = m0 & 4095;
    const float* W    = out_w + (size_t)layer*2*HH*HH;
    const float* bias = out_b + (size_t)layer*2*HH;
    const float* Ab   = g_yt  + (size_t)b*HH*LL;

    u64 acc0[8][2] = {}, acc1[8][2] = {};
    int tx = tid & 15, ty = tid >> 4;
    int am = tid & 127, ak0 = (tid >> 7) * 8;   // A loader: 128 m x 8 k each
    int bk = tid & 15,  bn  = tid >> 4;         // B loader: 16 k x 4 n-groups each

    for (int kk = 0; kk < HH; kk += 16) {
        #pragma unroll
        for (int j = 0; j < 8; j++)
            As[ak0 + j][am] = Ab[(size_t)(kk + ak0 + j)*LL + l0 + am];
        #pragma unroll
        for (int j = 0; j < 4; j++) {
            int nn = bn + 16*j;
            Bs0[bk][nn] = W[(size_t)(n0 + nn)*HH + kk + bk];
            Bs1[bk][nn] = W[(size_t)(HH + n0 + nn)*HH + kk + bk];
        }
        __syncthreads();
        #pragma unroll
        for (int k = 0; k < 16; k++) {
            float4 a0 = *(const float4*)&As[k][tx*8];
            float4 a1 = *(const float4*)&As[k][tx*8 + 4];
            u64 b00 = *(const u64*)&Bs0[k][ty*4];
            u64 b01 = *(const u64*)&Bs0[k][ty*4 + 2];
            u64 b10 = *(const u64*)&Bs1[k][ty*4];
            u64 b11 = *(const u64*)&Bs1[k][ty*4 + 2];
            float av[8] = {a0.x, a0.y, a0.z, a0.w, a1.x, a1.y, a1.z, a1.w};
            #pragma unroll
            for (int i = 0; i < 8; i++) {
                u64 ap = pk2(av[i], av[i]);
                acc0[i][0] = f2fma(ap, b00, acc0[i][0]);
                acc0[i][1] = f2fma(ap, b01, acc0[i][1]);
                acc1[i][0] = f2fma(ap, b10, acc1[i][0]);
                acc1[i][1] = f2fma(ap, b11, acc1[i][1]);
            }
        }
        __syncthreads();
    }

    int nb = n0 + ty*4;
    float bz0[4], bz1[4];
    #pragma unroll
    for (int j = 0; j < 4; j++) { bz0[j] = bias[nb + j]; bz1[j] = bias[HH + nb + j]; }
    #pragma unroll
    for (int i = 0; i < 8; i++) {
        int m = m0 + tx*8 + i;
        float4* p = (float4*)&g_h[(size_t)m*HH + nb];
        float4 hv = *p;
        float z0[4], z1[4];
        upk2(acc0[i][0], z0[0], z0[1]); upk2(acc0[i][1], z0[2], z0[3]);
        upk2(acc1[i][0], z1[0], z1[1]); upk2(acc1[i][1], z1[2], z1[3]);
        float g0 = (z0[0] + bz0[0]) / (1.0f + expf(-(z1[0] + bz1[0])));
        float g1 = (z0[1] + bz0[1]) / (1.0f + expf(-(z1[1] + bz1[1])));
        float g2 = (z0[2] + bz0[2]) / (1.0f + expf(-(z1[2] + bz1[2])));
        float g3 = (z0[3] + bz0[3]) / (1.0f + expf(-(z1[3] + bz1[3])));
        hv.x += g0; hv.y += g1; hv.z += g2; hv.w += g3;
        *p = hv;
    }
}

// ---------------- decoder -----------------------------------------------------
__global__ void __launch_bounds__(256) k_decoder(const float* __restrict__ dec_w,
                                                 const float* __restrict__ dec_b,
                                                 float* __restrict__ out) {
    int row  = blockIdx.x*8 + (threadIdx.x >> 5);
    int lane = threadIdx.x & 31;
    const float* hr = g_h + (size_t)row*HH;
    float s = 0.f;
    #pragma unroll
    for (int j = 0; j < 16; j++) s = fmaf(hr[lane + 32*j], dec_w[lane + 32*j], s);
    #pragma unroll
    for (int o = 16; o > 0; o >>= 1) s += __shfl_xor_sync(0xffffffffu, s, o);
    if (lane == 0) out[row] = s + dec_b[0];
}

// ---------------- driver ------------------------------------------------------
extern "C" void kernel_launch(void* const* d_in, const int* in_sizes, int n_in,
                              void* d_out, int out_size) {
    const float* x      = (const float*)d_in[0];
    const float* enc_w  = (const float*)d_in[1];
    const float* enc_b  = (const float*)d_in[2];
    const float* log_dt = (const float*)d_in[3];
    const float* A_re   = (const float*)d_in[4];
    const float* A_im   = (const float*)d_in[5];
    const float* C_re   = (const float*)d_in[6];
    const float* C_im   = (const float*)d_in[7];
    const float* D      = (const float*)d_in[8];
    const float* out_w  = (const float*)d_in[9];
    const float* out_b  = (const float*)d_in[10];
    const float* ln_w   = (const float*)d_in[11];
    const float* ln_b   = (const float*)d_in[12];
    const float* dec_w  = (const float*)d_in[13];
    const float* dec_b  = (const float*)d_in[14];
    float* out = (float*)d_out;

    k_params<<<(NLAYERS*HH*NN + 255)/256, 256>>>(log_dt, A_re, A_im, C_re, C_im);
    k_encoder<<<(BB*LL*HH)/256, 256>>>(x, enc_w, enc_b);

    for (int layer = 0; layer < NLAYERS; layer++) {
        dim3 lgrid(LL/32, BB);
        k_ln_t<<<lgrid, 256>>>(ln_w, ln_b, layer);
        k_scan<<<BB*HH, 256>>>(D, layer);
        dim3 ggrid(HH/64, (BB*LL)/128);
        k_gemm_glu<<<ggrid, 256>>>(out_w, out_b, layer);
    }
    k_decoder<<<(BB*LL)/8, 256>>>(dec_w, dec_b, out);
}

// round 5
// speedup vs baseline: 1.4921x; 1.4114x over previous
#include <cuda_runtime.h>
#include <cuda_bf16.h>
#include <cstdint>

#define BB 8
#define LL 4096
#define HH 512
#define NN 16
#define NLAYERS 4

typedef unsigned long long u64;

__device__ __forceinline__ u64 pk2(float lo, float hi) {
    u64 r; asm("mov.b64 %0,{%1,%2};" : "=l"(r) : "f"(lo), "f"(hi)); return r;
}
__device__ __forceinline__ void upk2(u64 v, float& lo, float& hi) {
    asm("mov.b64 {%0,%1},%2;" : "=f"(lo), "=f"(hi) : "l"(v));
}
__device__ __forceinline__ u64 f2fma(u64 a, u64 b, u64 c) {
    u64 d; asm("fma.rn.f32x2 %0,%1,%2,%3;" : "=l"(d) : "l"(a), "l"(b), "l"(c)); return d;
}
__device__ __forceinline__ uint32_t smem_u32(const void* p) {
    uint32_t a;
    asm("{ .reg .u64 t; cvta.to.shared.u64 t, %1; cvt.u32.u64 %0, t; }" : "=r"(a) : "l"(p));
    return a;
}
__device__ __forceinline__ void cpa16(uint32_t dst, const void* src) {
    asm volatile("cp.async.ca.shared.global [%0],[%1],16;" :: "r"(dst), "l"(src));
}

// ---------------- scratch ----------------------------------------------------
__device__ float g_h [BB*LL*HH];
__device__ float g_ut[(size_t)BB*HH*LL];
__device__ float g_yt[(size_t)BB*HH*LL];
__device__ float g_w [NLAYERS*HH*NN*2];
__device__ float g_ct[NLAYERS*2*HH*NN*2];
__device__ __nv_bfloat16 g_yh[(size_t)BB*LL*HH];
__device__ __nv_bfloat16 g_yl[(size_t)BB*LL*HH];
__device__ __nv_bfloat16 g_wh[NLAYERS*2*HH*HH];
__device__ __nv_bfloat16 g_wl[NLAYERS*2*HH*HH];

// ---------------- SSM parameter precompute ----------------------------------
__global__ void k_params(const float* __restrict__ log_dt, const float* __restrict__ A_re,
                         const float* __restrict__ A_im, const float* __restrict__ C_re,
                         const float* __restrict__ C_im) {
    int idx = blockIdx.x * blockDim.x + threadIdx.x;
    if (idx >= NLAYERS*HH*NN) return;
    int n     = idx % NN;
    int h     = (idx / NN) % HH;
    int layer = idx / (HH*NN);
    float dt  = expf(log_dt[layer*HH + h]);
    float are = A_re[idx];
    float aim = A_im[idx];
    float e   = expf(are*dt);
    float wre = e * cosf(aim*dt);
    float wim = e * sinf(aim*dt);
    g_w[idx*2+0] = wre;
    g_w[idx*2+1] = wim;
    float inv = 1.0f / (are*are + aim*aim);
    float nre = wre - 1.0f, nim = wim;
    float fre = (nre*are + nim*aim) * inv;
    float fim = (nim*are - nre*aim) * inv;
    #pragma unroll
    for (int c = 0; c < 2; c++) {
        int cidx = ((layer*2 + c)*HH + h)*NN + n;
        float cre = C_re[cidx], cim = C_im[cidx];
        g_ct[cidx*2+0] = 2.0f*(cre*fre - cim*fim);
        g_ct[cidx*2+1] = 2.0f*(cre*fim + cim*fre);
    }
}

// ---------------- W split into bf16 hi/lo ------------------------------------
__global__ void k_wsplit(const float* __restrict__ out_w) {
    int idx = blockIdx.x * blockDim.x + threadIdx.x;
    float v = out_w[idx];
    __nv_bfloat16 hi = __float2bfloat16(v);
    g_wh[idx] = hi;
    g_wl[idx] = __float2bfloat16(v - __bfloat162float(hi));
}

// ---------------- encoder ----------------------------------------------------
__global__ void k_encoder(const float* __restrict__ x, const float* __restrict__ enc_w,
                          const float* __restrict__ enc_b) {
    int idx = blockIdx.x * blockDim.x + threadIdx.x;
    int hh = idx % HH;
    int l  = (idx / HH) % LL;
    int b  = idx / (LL*HH);
    float grid = (float)l * (1.0f/(LL-1));
    g_h[idx] = enc_w[hh*2+0]*x[b*LL + l] + enc_w[hh*2+1]*grid + enc_b[hh];
}

// ---------------- LayerNorm + transpose to (B,H,L) ---------------------------
__global__ void __launch_bounds__(256) k_ln_t(const float* __restrict__ ln_w,
                                              const float* __restrict__ ln_b, int layer) {
    __shared__ float s_mean[32], s_rstd[32];
    __shared__ float tile[64][33];
    int b  = blockIdx.y;
    int l0 = blockIdx.x * 32;
    int tid = threadIdx.x, warp = tid >> 5, lane = tid & 31;
    const float* lw = ln_w + layer*HH;
    const float* lb = ln_b + layer*HH;

    for (int r = warp; r < 32; r += 8) {
        const float* row = g_h + ((size_t)b*LL + l0 + r)*HH;
        float sum = 0.f, sq = 0.f;
        #pragma unroll
        for (int j = 0; j < 16; j++) { float v = row[lane + 32*j]; sum += v; sq += v*v; }
        #pragma unroll
        for (int o = 16; o > 0; o >>= 1) {
            sum += __shfl_xor_sync(0xffffffffu, sum, o);
            sq  += __shfl_xor_sync(0xffffffffu, sq , o);
        }
        if (lane == 0) {
            float mu = sum * (1.0f/HH);
            s_mean[r] = mu;
            s_rstd[r] = rsqrtf(sq * (1.0f/HH) - mu*mu + 1e-5f);
        }
    }
    __syncthreads();

    for (int h0 = 0; h0 < HH; h0 += 64) {
        #pragma unroll
        for (int p = 0; p < 8; p++) {
            int r = p*4 + (tid >> 6);
            int c = tid & 63;
            float v = g_h[((size_t)b*LL + l0 + r)*HH + h0 + c];
            tile[c][r] = (v - s_mean[r]) * s_rstd[r] * lw[h0 + c] + lb[h0 + c];
        }
        __syncthreads();
        #pragma unroll
        for (int p = 0; p < 8; p++) {
            int hh = p*8 + (tid >> 5);
            int lc = tid & 31;
            g_ut[((size_t)b*HH + h0 + hh)*LL + l0 + lc] = tile[hh][lc];
        }
        __syncthreads();
    }
}

// ---------------- bidirectional SSM scan, packed-across-n --------------------
// 256 threads = 32 chunks(128 steps) x 2 dirs x 4 n-threads (4 n each, 2 pairs).
__global__ void __launch_bounds__(256) k_scan(const float* __restrict__ Din, int layer) {
    __shared__ float su[4129];       // skewed: idx = t + (t>>7); su[4128] = 0 pad
    __shared__ float sy[4129];
    __shared__ u64 st[64*4*4];       // chunk sums, overwritten in-place with carries

    int bh = blockIdx.x;
    int h  = bh & 511;
    int tid = threadIdx.x;
    const float* urow = g_ut + (size_t)bh * LL;

    for (int t = tid; t < 4096; t += 256) su[t + (t >> 7)] = urow[t];
    if (tid == 0) su[4128] = 0.0f;
    __syncthreads();

    float Dh = Din[layer*HH + h];
    for (int t = tid; t < 4096; t += 256) {
        int ts = t + (t >> 7);
        sy[ts] = Dh * su[ts];
    }

    int n4    = tid & 3;
    int dir   = (tid >> 2) & 1;
    int chunk = tid >> 3;
    int t0    = chunk << 7;

    const float* wb = g_w  + (size_t)(layer*HH + h)*NN*2;
    const float* cb = g_ct + (size_t)((layer*2 + dir)*HH + h)*NN*2;
    u64 wre2[2], wim2[2], nwim2[2], cre2[2], ncim2[2];
    #pragma unroll
    for (int p = 0; p < 2; p++) {
        int na = n4 + 8*p, nb = na + 4;
        float wra = wb[2*na], wia = wb[2*na+1], wrb = wb[2*nb], wib = wb[2*nb+1];
        wre2[p]  = pk2(wra, wrb);
        wim2[p]  = pk2(wia, wib);
        nwim2[p] = pk2(-wia, -wib);
        cre2[p]  = pk2(cb[2*na], cb[2*nb]);
        ncim2[p] = pk2(-cb[2*na+1], -cb[2*nb+1]);
    }
    const u64 ZERO = 0ULL;

    // pass 1: chunk-local sums from zero state
    u64 sre[2] = {0ULL, 0ULL}, sim[2] = {0ULL, 0ULL};
    #pragma unroll 4
    for (int i = 0; i < 128; i++) {
        int t = dir ? (t0 + 128 - i) : (t0 + i);
        float u = su[t + (t >> 7)];
        u64 u2 = pk2(u, u);
        #pragma unroll
        for (int p = 0; p < 2; p++) {
            u64 tre = f2fma(wre2[p], sre[p], u2);
            tre     = f2fma(nwim2[p], sim[p], tre);
            u64 tim = f2fma(wim2[p], sre[p], ZERO);
            tim     = f2fma(wre2[p], sim[p], tim);
            sre[p] = tre; sim[p] = tim;
        }
    }
    {
        int s = ((dir*32 + chunk)*4 + n4)*4;
        st[s+0] = sre[0]; st[s+1] = sim[0]; st[s+2] = sre[1]; st[s+3] = sim[1];
    }
    __syncthreads();

    // combine: 16 threads; in-place replace chunk sums with entering carries
    if (tid < 16) {
        int d = tid >> 3, p = (tid >> 2) & 1, nn4 = tid & 3;
        int na = nn4 + 8*p, nb = na + 4;
        float ra = wb[2*na], ia = wb[2*na+1], rb = wb[2*nb], ib = wb[2*nb+1];
        #pragma unroll
        for (int q = 0; q < 7; q++) {           // w^128
            float t1 = ra*ra - ia*ia; ia = 2.0f*ra*ia; ra = t1;
            float t2 = rb*rb - ib*ib; ib = 2.0f*rb*ib; rb = t2;
        }
        u64 Pre = pk2(ra, rb), Pim = pk2(ia, ib), nPim = pk2(-ia, -ib);
        u64 Fre = 0ULL, Fim = 0ULL;
        if (d == 0) {
            for (int c = 0; c < 32; c++) {
                int s = (c*4 + nn4)*4 + 2*p;
                u64 Sre = st[s], Sim = st[s+1];
                st[s] = Fre; st[s+1] = Fim;
                u64 t1 = f2fma(Pre, Fre, Sre);
                u64 nFre = f2fma(nPim, Fim, t1);
                u64 t2 = f2fma(Pre, Fim, Sim);
                u64 nFim = f2fma(Pim, Fre, t2);
                Fre = nFre; Fim = nFim;
            }
        } else {
            for (int c = 31; c >= 0; c--) {
                int s = ((32 + c)*4 + nn4)*4 + 2*p;
                u64 Sre = st[s], Sim = st[s+1];
                st[s] = Fre; st[s+1] = Fim;
                u64 t1 = f2fma(Pre, Fre, Sre);
                u64 nFre = f2fma(nPim, Fim, t1);
                u64 t2 = f2fma(Pre, Fim, Sim);
                u64 nFim = f2fma(Pim, Fre, t2);
                Fre = nFre; Fim = nFim;
            }
        }
    }
    __syncthreads();

    // pass 2: full scan with carries
    {
        int s = ((dir*32 + chunk)*4 + n4)*4;
        sre[0] = st[s+0]; sim[0] = st[s+1]; sre[1] = st[s+2]; sim[1] = st[s+3];
    }
    #pragma unroll 4
    for (int i = 0; i < 128; i++) {
        int tout = dir ? (t0 + 127 - i) : (t0 + i);
        int tu   = tout + dir;
        float u  = su[tu + (tu >> 7)];
        u64 u2 = pk2(u, u);
        u64 v2 = 0ULL;
        #pragma unroll
        for (int p = 0; p < 2; p++) {
            u64 tre = f2fma(wre2[p], sre[p], u2);
            tre     = f2fma(nwim2[p], sim[p], tre);
            u64 tim = f2fma(wim2[p], sre[p], ZERO);
            tim     = f2fma(wre2[p], sim[p], tim);
            sre[p] = tre; sim[p] = tim;
            v2 = f2fma(cre2[p], tre, v2);
            v2 = f2fma(ncim2[p], tim, v2);
        }
        float va, vb; upk2(v2, va, vb);
        float v = va + vb;
        v += __shfl_xor_sync(0xffffffffu, v, 1);
        v += __shfl_xor_sync(0xffffffffu, v, 2);
        if (n4 == 0) sy[tout + (tout >> 7)] += v;
    }
    __syncthreads();

    // epilogue: exact-erf GELU, write (B,H,L)
    float* orow = g_yt + (size_t)bh * LL;
    for (int t = tid; t < 4096; t += 256) {
        float v = sy[t + (t >> 7)];
        orow[t] = 0.5f * v * (1.0f + erff(v * 0.70710678118f));
    }
}

// ---------------- transpose + bf16 hi/lo split: (B,H,L) -> (B,L,H) -----------
__global__ void __launch_bounds__(256) k_split() {
    __shared__ float t[32][33];
    int b  = blockIdx.z;
    int h0 = blockIdx.y * 32;
    int l0 = blockIdx.x * 32;
    int tid = threadIdx.x, lane = tid & 31, r = tid >> 5;
    #pragma unroll
    for (int q = 0; q < 4; q++) {
        int hh = r + 8*q;
        t[hh][lane] = g_yt[((size_t)(b*HH + h0 + hh))*LL + l0 + lane];
    }
    __syncthreads();
    #pragma unroll
    for (int q = 0; q < 4; q++) {
        int ll = r + 8*q;
        float v = t[lane][ll];
        __nv_bfloat16 hi = __float2bfloat16(v);
        size_t o = ((size_t)(b*LL + l0 + ll))*HH + h0 + lane;
        g_yh[o] = hi;
        g_yl[o] = __float2bfloat16(v - __bfloat162float(hi));
    }
}

// ---------------- bf16 HMMA GEMM (3-term split) + GLU + residual -------------
// CTA tile 128m x 128n (64 z0-cols + paired 64 z1-cols), K = 3 passes x 512.
// 8 warps as 4m x 2n; warp tile 32m x 64n. smem rows strided 80B (conflict-free
// ldmatrix: j*80 mod 128 covers all 8 16B-slots). Double-buffered cp.async.
__global__ void __launch_bounds__(256) k_mma_glu(const float* __restrict__ out_b, int layer) {
    __shared__ alignas(16) char smraw[40960];   // 2 bufs x (A 10240 + B 10240)
    int tid = threadIdx.x, warp = tid >> 5, lane = tid & 31;
    int wm = warp & 3, wn = warp >> 2;
    int n0 = blockIdx.x * 64;
    int m0 = blockIdx.y * 128;
    uint32_t sbase = smem_u32(smraw);

    const __nv_bfloat16* Wl = g_wh + (size_t)layer*2*HH*HH;   // rebased per pass
    const __nv_bfloat16* Wll = g_wl + (size_t)layer*2*HH*HH;

    float acc[2][8][4];
    #pragma unroll
    for (int a = 0; a < 2; a++)
        #pragma unroll
        for (int b = 0; b < 8; b++)
            #pragma unroll
            for (int c = 0; c < 4; c++) acc[a][b][c] = 0.f;

    // per-thread load mapping: 2 chunks of A + 2 of B
    int ch0 = tid, ch1 = tid + 256;
    int ar0 = ch0 >> 2, ac0 = ch0 & 3, ar1 = ch1 >> 2, ac1 = ch1 & 3;
    int wr0 = (ar0 < 64) ? (n0 + ar0) : (448 + n0 + ar0);
    int wr1 = (ar1 < 64) ? (n0 + ar1) : (448 + n0 + ar1);

    // ldmatrix per-lane address pieces
    int rl = lane & 7, q2 = (lane >> 3) & 1, q1 = lane >> 4;

    #define LOADT(it, buf) do {                                                  \
        int pass_ = (it) >> 4, k0_ = ((it) & 15) << 5;                           \
        const __nv_bfloat16* Y_ = (pass_ < 2) ? g_yh : g_yl;                     \
        const __nv_bfloat16* W_ = (pass_ == 1) ? Wll : Wl;                       \
        uint32_t Ab_ = sbase + (buf)*20480;                                      \
        uint32_t Bb_ = Ab_ + 10240;                                              \
        cpa16(Ab_ + ar0*80 + ac0*16, Y_ + (size_t)(m0 + ar0)*HH + k0_ + ac0*8);  \
        cpa16(Ab_ + ar1*80 + ac1*16, Y_ + (size_t)(m0 + ar1)*HH + k0_ + ac1*8);  \
        cpa16(Bb_ + ar0*80 + ac0*16, W_ + (size_t)wr0*HH + k0_ + ac0*8);         \
        cpa16(Bb_ + ar1*80 + ac1*16, W_ + (size_t)wr1*HH + k0_ + ac1*8);         \
        asm volatile("cp.async.commit_group;");                                  \
    } while (0)

    LOADT(0, 0);
    for (int it = 0; it < 48; it++) {
        int buf = it & 1;
        if (it + 1 < 48) {
            LOADT(it + 1, buf ^ 1);
            asm volatile("cp.async.wait_group 1;");
        } else {
            asm volatile("cp.async.wait_group 0;");
        }
        __syncthreads();

        uint32_t Ab = sbase + buf*20480;
        uint32_t Bb = Ab + 10240;
        #pragma unroll
        for (int ks = 0; ks < 2; ks++) {
            int cb = ks << 1;
            uint32_t a[2][4];
            #pragma unroll
            for (int mf = 0; mf < 2; mf++) {
                int row = (wm << 5) + (mf << 4) + (q2 << 3) + rl;
                uint32_t ad = Ab + row*80 + (cb + q1)*16;
                asm volatile("ldmatrix.sync.aligned.m8n8.x4.shared.b16 {%0,%1,%2,%3}, [%4];"
                             : "=r"(a[mf][0]), "=r"(a[mf][1]), "=r"(a[mf][2]), "=r"(a[mf][3])
                             : "r"(ad));
            }
            #pragma unroll
            for (int q = 0; q < 4; q++) {
                int nrow = (wn << 6) + (q << 4) + (q2 << 3) + rl;
                uint32_t bd = Bb + nrow*80 + (cb + q1)*16;
                uint32_t b0, b1, b2, b3;
                asm volatile("ldmatrix.sync.aligned.m8n8.x4.shared.b16 {%0,%1,%2,%3}, [%4];"
                             : "=r"(b0), "=r"(b1), "=r"(b2), "=r"(b3) : "r"(bd));
                #pragma unroll
                for (int mf = 0; mf < 2; mf++) {
                    asm volatile("mma.sync.aligned.m16n8k16.row.col.f32.bf16.bf16.f32 "
                        "{%0,%1,%2,%3},{%4,%5,%6,%7},{%8,%9},{%0,%1,%2,%3};"
                        : "+f"(acc[mf][2*q][0]), "+f"(acc[mf][2*q][1]),
                          "+f"(acc[mf][2*q][2]), "+f"(acc[mf][2*q][3])
                        : "r"(a[mf][0]), "r"(a[mf][1]), "r"(a[mf][2]), "r"(a[mf][3]),
                          "r"(b0), "r"(b2));
                    asm volatile("mma.sync.aligned.m16n8k16.row.col.f32.bf16.bf16.f32 "
                        "{%0,%1,%2,%3},{%4,%5,%6,%7},{%8,%9},{%0,%1,%2,%3};"
                        : "+f"(acc[mf][2*q+1][0]), "+f"(acc[mf][2*q+1][1]),
                          "+f"(acc[mf][2*q+1][2]), "+f"(acc[mf][2*q+1][3])
                        : "r"(a[mf][0]), "r"(a[mf][1]), "r"(a[mf][2]), "r"(a[mf][3]),
                          "r"(b1), "r"(b3));
                }
            }
        }
        __syncthreads();
    }
    #undef LOADT

    // epilogue: z1 warps publish (z1+b1) via smem; z0 warps apply GLU + residual
    float* sb = (float*)smraw;
    const float* bias = out_b + (size_t)layer*1024 + n0;
    if (wn == 1) {
        #pragma unroll
        for (int mf = 0; mf < 2; mf++)
            #pragma unroll
            for (int nf = 0; nf < 8; nf++)
                #pragma unroll
                for (int r = 0; r < 4; r++) {
                    int row = mf*16 + (lane >> 2) + ((r >> 1) << 3);
                    int col = nf*8 + ((lane & 3) << 1) + (r & 1);
                    sb[(wm << 11) + (row << 6) + col] = acc[mf][nf][r] + bias[512 + col];
                }
    }
    __syncthreads();
    if (wn == 0) {
        #pragma unroll
        for (int mf = 0; mf < 2; mf++)
            #pragma unroll
            for (int nf = 0; nf < 8; nf++)
                #pragma unroll
                for (int r = 0; r < 4; r++) {
                    int row = mf*16 + (lane >> 2) + ((r >> 1) << 3);
                    int col = nf*8 + ((lane & 3) << 1) + (r & 1);
                    float z0 = acc[mf][nf][r] + bias[col];
                    float z1 = sb[(wm << 11) + (row << 6) + col];
                    float g  = z0 / (1.0f + expf(-z1));
                    g_h[(size_t)(m0 + wm*32 + row)*HH + n0 + col] += g;
                }
    }
}

// ---------------- decoder -----------------------------------------------------
__global__ void __launch_bounds__(256) k_decoder(const float* __restrict__ dec_w,
                                                 const float* __restrict__ dec_b,
                                                 float* __restrict__ out) {
    int row  = blockIdx.x*8 + (threadIdx.x >> 5);
    int lane = threadIdx.x & 31;
    const float* hr = g_h + (size_t)row*HH;
    float s = 0.f;
    #pragma unroll
    for (int j = 0; j < 16; j++) s = fmaf(hr[lane + 32*j], dec_w[lane + 32*j], s);
    #pragma unroll
    for (int o = 16; o > 0; o >>= 1) s += __shfl_xor_sync(0xffffffffu, s, o);
    if (lane == 0) out[row] = s + dec_b[0];
}

// ---------------- driver ------------------------------------------------------
extern "C" void kernel_launch(void* const* d_in, const int* in_sizes, int n_in,
                              void* d_out, int out_size) {
    const float* x      = (const float*)d_in[0];
    const float* enc_w  = (const float*)d_in[1];
    const float* enc_b  = (const float*)d_in[2];
    const float* log_dt = (const float*)d_in[3];
    const float* A_re   = (const float*)d_in[4];
    const float* A_im   = (const float*)d_in[5];
    const float* C_re   = (const float*)d_in[6];
    const float* C_im   = (const float*)d_in[7];
    const float* D      = (const float*)d_in[8];
    const float* out_w  = (const float*)d_in[9];
    const float* out_b  = (const float*)d_in[10];
    const float* ln_w   = (const float*)d_in[11];
    const float* ln_b   = (const float*)d_in[12];
    const float* dec_w  = (const float*)d_in[13];
    const float* dec_b  = (const float*)d_in[14];
    float* out = (float*)d_out;

    k_params<<<(NLAYERS*HH*NN + 255)/256, 256>>>(log_dt, A_re, A_im, C_re, C_im);
    k_wsplit<<<(NLAYERS*2*HH*HH)/256, 256>>>(out_w);
    k_encoder<<<(BB*LL*HH)/256, 256>>>(x, enc_w, enc_b);

    for (int layer = 0; layer < NLAYERS; layer++) {
        dim3 lgrid(LL/32, BB);
        k_ln_t<<<lgrid, 256>>>(ln_w, ln_b, layer);
        k_scan<<<BB*HH, 256>>>(D, layer);
        dim3 sgrid(LL/32, HH/32, BB);
        k_split<<<sgrid, 256>>>();
        dim3 ggrid(HH/64, (BB*LL)/128);
        k_mma_glu<<<ggrid, 256>>>(out_b, layer);
    }
    k_decoder<<<(BB*LL)/8, 256>>>(dec_w, dec_b, out);
}

// round 6
// speedup vs baseline: 1.7707x; 1.1867x over previous
#include <cuda_runtime.h>
#include <cuda_fp16.h>
#include <cstdint>

#define BB 8
#define LL 4096
#define HH 512
#define NN 16
#define NLAYERS 4

typedef unsigned long long u64;

__device__ __forceinline__ u64 pk2(float lo, float hi) {
    u64 r; asm("mov.b64 %0,{%1,%2};" : "=l"(r) : "f"(lo), "f"(hi)); return r;
}
__device__ __forceinline__ void upk2(u64 v, float& lo, float& hi) {
    asm("mov.b64 {%0,%1},%2;" : "=f"(lo), "=f"(hi) : "l"(v));
}
__device__ __forceinline__ u64 f2fma(u64 a, u64 b, u64 c) {
    u64 d; asm("fma.rn.f32x2 %0,%1,%2,%3;" : "=l"(d) : "l"(a), "l"(b), "l"(c)); return d;
}
__device__ __forceinline__ uint32_t smem_u32(const void* p) {
    uint32_t a;
    asm("{ .reg .u64 t; cvta.to.shared.u64 t, %1; cvt.u32.u64 %0, t; }" : "=r"(a) : "l"(p));
    return a;
}
__device__ __forceinline__ void cpa16(uint32_t dst, const void* src) {
    asm volatile("cp.async.cg.shared.global [%0],[%1],16;" :: "r"(dst), "l"(src));
}

// ---------------- scratch ----------------------------------------------------
__device__ float g_h [BB*LL*HH];
__device__ float g_ut[(size_t)BB*HH*LL];
__device__ float g_yt[(size_t)BB*HH*LL];
__device__ float g_w [NLAYERS*HH*NN*2];
__device__ float g_ct[NLAYERS*2*HH*NN*2];
__device__ __half g_yh[(size_t)BB*LL*HH];
__device__ __half g_yl[(size_t)BB*LL*HH];
__device__ __half g_wh[NLAYERS*2*HH*HH];

// ---------------- SSM parameter precompute ----------------------------------
__global__ void k_params(const float* __restrict__ log_dt, const float* __restrict__ A_re,
                         const float* __restrict__ A_im, const float* __restrict__ C_re,
                         const float* __restrict__ C_im) {
    int idx = blockIdx.x * blockDim.x + threadIdx.x;
    if (idx >= NLAYERS*HH*NN) return;
    int n     = idx % NN;
    int h     = (idx / NN) % HH;
    int layer = idx / (HH*NN);
    float dt  = expf(log_dt[layer*HH + h]);
    float are = A_re[idx];
    float aim = A_im[idx];
    float e   = expf(are*dt);
    float wre = e * cosf(aim*dt);
    float wim = e * sinf(aim*dt);
    g_w[idx*2+0] = wre;
    g_w[idx*2+1] = wim;
    float inv = 1.0f / (are*are + aim*aim);
    float nre = wre - 1.0f, nim = wim;
    float fre = (nre*are + nim*aim) * inv;
    float fim = (nim*are - nre*aim) * inv;
    #pragma unroll
    for (int c = 0; c < 2; c++) {
        int cidx = ((layer*2 + c)*HH + h)*NN + n;
        float cre = C_re[cidx], cim = C_im[cidx];
        g_ct[cidx*2+0] = 2.0f*(cre*fre - cim*fim);
        g_ct[cidx*2+1] = 2.0f*(cre*fim + cim*fre);
    }
}

// ---------------- W -> fp16 --------------------------------------------------
__global__ void k_wsplit(const float* __restrict__ out_w) {
    int idx = blockIdx.x * blockDim.x + threadIdx.x;
    g_wh[idx] = __float2half(out_w[idx]);
}

// ---------------- encoder ----------------------------------------------------
__global__ void k_encoder(const float* __restrict__ x, const float* __restrict__ enc_w,
                          const float* __restrict__ enc_b) {
    int idx = blockIdx.x * blockDim.x + threadIdx.x;
    int hh = idx % HH;
    int l  = (idx / HH) % LL;
    int b  = idx / (LL*HH);
    float grid = (float)l * (1.0f/(LL-1));
    g_h[idx] = enc_w[hh*2+0]*x[b*LL + l] + enc_w[hh*2+1]*grid + enc_b[hh];
}

// ---------------- LayerNorm + transpose to (B,H,L) ---------------------------
__global__ void __launch_bounds__(256) k_ln_t(const float* __restrict__ ln_w,
                                              const float* __restrict__ ln_b, int layer) {
    __shared__ float s_mean[32], s_rstd[32];
    __shared__ float tile[64][33];
    int b  = blockIdx.y;
    int l0 = blockIdx.x * 32;
    int tid = threadIdx.x, warp = tid >> 5, lane = tid & 31;
    const float* lw = ln_w + layer*HH;
    const float* lb = ln_b + layer*HH;

    for (int r = warp; r < 32; r += 8) {
        const float* row = g_h + ((size_t)b*LL + l0 + r)*HH;
        float sum = 0.f, sq = 0.f;
        #pragma unroll
        for (int j = 0; j < 16; j++) { float v = row[lane + 32*j]; sum += v; sq += v*v; }
        #pragma unroll
        for (int o = 16; o > 0; o >>= 1) {
            sum += __shfl_xor_sync(0xffffffffu, sum, o);
            sq  += __shfl_xor_sync(0xffffffffu, sq , o);
        }
        if (lane == 0) {
            float mu = sum * (1.0f/HH);
            s_mean[r] = mu;
            s_rstd[r] = rsqrtf(sq * (1.0f/HH) - mu*mu + 1e-5f);
        }
    }
    __syncthreads();

    for (int h0 = 0; h0 < HH; h0 += 64) {
        #pragma unroll
        for (int p = 0; p < 8; p++) {
            int r = p*4 + (tid >> 6);
            int c = tid & 63;
            float v = g_h[((size_t)b*LL + l0 + r)*HH + h0 + c];
            tile[c][r] = (v - s_mean[r]) * s_rstd[r] * lw[h0 + c] + lb[h0 + c];
        }
        __syncthreads();
        #pragma unroll
        for (int p = 0; p < 8; p++) {
            int hh = p*8 + (tid >> 5);
            int lc = tid & 31;
            g_ut[((size_t)b*HH + h0 + hh)*LL + l0 + lc] = tile[hh][lc];
        }
        __syncthreads();
    }
}

// ---------------- bidirectional SSM scan -------------------------------------
// 256 threads = 32 chunks(128 steps) x 2 dirs x 4 n-threads (4 n each, 2 pairs).
__global__ void __launch_bounds__(256) k_scan(const float* __restrict__ Din, int layer) {
    __shared__ float su[4129];       // skewed: idx = t + (t>>7); su[4128] = 0 pad
    __shared__ float sy[4129];
    __shared__ u64 st[64*4*4];       // chunk sums, replaced in-place by carries

    int bh = blockIdx.x;
    int h  = bh & 511;
    int tid = threadIdx.x;
    const float* urow = g_ut + (size_t)bh * LL;

    for (int t = tid; t < 4096; t += 256) su[t + (t >> 7)] = urow[t];
    if (tid == 0) su[4128] = 0.0f;
    __syncthreads();

    float Dh = Din[layer*HH + h];
    for (int t = tid; t < 4096; t += 256) {
        int ts = t + (t >> 7);
        sy[ts] = Dh * su[ts];
    }

    int n4    = tid & 3;
    int dir   = (tid >> 2) & 1;
    int chunk = tid >> 3;
    int t0    = chunk << 7;

    const float* wb = g_w  + (size_t)(layer*HH + h)*NN*2;
    const float* cb = g_ct + (size_t)((layer*2 + dir)*HH + h)*NN*2;
    u64 wre2[2], wim2[2], nwim2[2], cre2[2], ncim2[2];
    u64 w2re2[2], w2im2[2], nw2im2[2];
    #pragma unroll
    for (int p = 0; p < 2; p++) {
        int na = n4 + 8*p, nb = na + 4;
        float wra = wb[2*na], wia = wb[2*na+1], wrb = wb[2*nb], wib = wb[2*nb+1];
        wre2[p]  = pk2(wra, wrb);
        wim2[p]  = pk2(wia, wib);
        nwim2[p] = pk2(-wia, -wib);
        cre2[p]  = pk2(cb[2*na], cb[2*nb]);
        ncim2[p] = pk2(-cb[2*na+1], -cb[2*nb+1]);
        float w2ra = wra*wra - wia*wia, w2ia = 2.0f*wra*wia;
        float w2rb = wrb*wrb - wib*wib, w2ib = 2.0f*wrb*wib;
        w2re2[p]  = pk2(w2ra, w2rb);
        w2im2[p]  = pk2(w2ia, w2ib);
        nw2im2[p] = pk2(-w2ia, -w2ib);
    }
    const u64 ZERO = 0ULL;
    int stp = dir ? -1 : 1;

    // pass 1: chunk-local sums, 2 steps per iteration via w^2
    u64 sre[2] = {0ULL, 0ULL}, sim[2] = {0ULL, 0ULL};
    #pragma unroll 2
    for (int j = 0; j < 64; j++) {
        int ta = dir ? (t0 + 128 - 2*j) : (t0 + 2*j);
        int tb = ta + stp;
        float u1 = su[ta + (ta >> 7)];
        float u2 = su[tb + (tb >> 7)];
        u64 u1_2 = pk2(u1, u1);
        u64 u2_2 = pk2(u2, u2);
        #pragma unroll
        for (int p = 0; p < 2; p++) {
            u64 qre = f2fma(wre2[p], u1_2, u2_2);     // w.re*u1 + u2
            u64 qim = f2fma(wim2[p], u1_2, ZERO);     // w.im*u1
            u64 tre = f2fma(w2re2[p], sre[p], qre);
            tre     = f2fma(nw2im2[p], sim[p], tre);
            u64 tim = f2fma(w2im2[p], sre[p], qim);
            tim     = f2fma(w2re2[p], sim[p], tim);
            sre[p] = tre; sim[p] = tim;
        }
    }
    {
        int s = ((dir*32 + chunk)*4 + n4)*4;
        st[s+0] = sre[0]; st[s+1] = sim[0]; st[s+2] = sre[1]; st[s+3] = sim[1];
    }
    __syncthreads();

    // combine: 16 threads; in-place replace chunk sums with entering carries
    if (tid < 16) {
        int d = tid >> 3, p = (tid >> 2) & 1, nn4 = tid & 3;
        int na = nn4 + 8*p, nb = na + 4;
        float ra = wb[2*na], ia = wb[2*na+1], rb = wb[2*nb], ib = wb[2*nb+1];
        #pragma unroll
        for (int q = 0; q < 7; q++) {           // w^128
            float t1 = ra*ra - ia*ia; ia = 2.0f*ra*ia; ra = t1;
            float t2 = rb*rb - ib*ib; ib = 2.0f*rb*ib; rb = t2;
        }
        u64 Pre = pk2(ra, rb), Pim = pk2(ia, ib), nPim = pk2(-ia, -ib);
        u64 Fre = 0ULL, Fim = 0ULL;
        if (d == 0) {
            for (int c = 0; c < 32; c++) {
                int s = (c*4 + nn4)*4 + 2*p;
                u64 Sre = st[s], Sim = st[s+1];
                st[s] = Fre; st[s+1] = Fim;
                u64 t1 = f2fma(Pre, Fre, Sre);
                u64 nFre = f2fma(nPim, Fim, t1);
                u64 t2 = f2fma(Pre, Fim, Sim);
                u64 nFim = f2fma(Pim, Fre, t2);
                Fre = nFre; Fim = nFim;
            }
        } else {
            for (int c = 31; c >= 0; c--) {
                int s = ((32 + c)*4 + nn4)*4 + 2*p;
                u64 Sre = st[s], Sim = st[s+1];
                st[s] = Fre; st[s+1] = Fim;
                u64 t1 = f2fma(Pre, Fre, Sre);
                u64 nFre = f2fma(nPim, Fim, t1);
                u64 t2 = f2fma(Pre, Fim, Sim);
                u64 nFim = f2fma(Pim, Fre, t2);
                Fre = nFre; Fim = nFim;
            }
        }
    }
    __syncthreads();

    // pass 2: full scan with carries, emit per timestep
    {
        int s = ((dir*32 + chunk)*4 + n4)*4;
        sre[0] = st[s+0]; sim[0] = st[s+1]; sre[1] = st[s+2]; sim[1] = st[s+3];
    }
    #pragma unroll 4
    for (int i = 0; i < 128; i++) {
        int tout = dir ? (t0 + 127 - i) : (t0 + i);
        int tu   = tout + dir;
        float u  = su[tu + (tu >> 7)];
        u64 u2 = pk2(u, u);
        u64 v2 = 0ULL;
        #pragma unroll
        for (int p = 0; p < 2; p++) {
            u64 tre = f2fma(wre2[p], sre[p], u2);
            tre     = f2fma(nwim2[p], sim[p], tre);
            u64 tim = f2fma(wim2[p], sre[p], ZERO);
            tim     = f2fma(wre2[p], sim[p], tim);
            sre[p] = tre; sim[p] = tim;
            v2 = f2fma(cre2[p], tre, v2);
            v2 = f2fma(ncim2[p], tim, v2);
        }
        float va, vb; upk2(v2, va, vb);
        float v = va + vb;
        v += __shfl_xor_sync(0xffffffffu, v, 1);
        v += __shfl_xor_sync(0xffffffffu, v, 2);
        if (n4 == 0) sy[tout + (tout >> 7)] += v;
    }
    __syncthreads();

    // epilogue: exact-erf GELU, write (B,H,L)
    float* orow = g_yt + (size_t)bh * LL;
    for (int t = tid; t < 4096; t += 256) {
        float v = sy[t + (t >> 7)];
        orow[t] = 0.5f * v * (1.0f + erff(v * 0.70710678118f));
    }
}

// ---------------- transpose + fp16 hi/lo split: (B,H,L) -> (B,L,H) -----------
__global__ void __launch_bounds__(256) k_split() {
    __shared__ float t[32][33];
    int b  = blockIdx.z;
    int h0 = blockIdx.y * 32;
    int l0 = blockIdx.x * 32;
    int tid = threadIdx.x, lane = tid & 31, r = tid >> 5;
    #pragma unroll
    for (int q = 0; q < 4; q++) {
        int hh = r + 8*q;
        t[hh][lane] = g_yt[((size_t)(b*HH + h0 + hh))*LL + l0 + lane];
    }
    __syncthreads();
    #pragma unroll
    for (int q = 0; q < 4; q++) {
        int ll = r + 8*q;
        float v = t[lane][ll];
        __half hi = __float2half(v);
        size_t o = ((size_t)(b*LL + l0 + ll))*HH + h0 + lane;
        g_yh[o] = hi;
        g_yl[o] = __float2half(v - __half2float(hi));
    }
}

// ---------------- fp16 HMMA GEMM (2-term split) + GLU + residual -------------
// CTA tile 128m x 128n (64 z0-cols + paired 64 z1-cols), 16 k-slices x 2 passes.
// B (weights) loaded once per k-slice, reused by both A passes (yh, yl).
__global__ void __launch_bounds__(256) k_mma_glu(const float* __restrict__ out_b, int layer) {
    __shared__ alignas(16) char smraw[40960];   // A: 2 x 10240 | B: 2 x 10240
    int tid = threadIdx.x, warp = tid >> 5, lane = tid & 31;
    int wm = warp & 3, wn = warp >> 2;
    int n0 = blockIdx.x * 64;
    int m0 = blockIdx.y * 128;
    uint32_t sbase = smem_u32(smraw);

    const __half* Wh = g_wh + (size_t)layer*2*HH*HH;

    float acc[2][8][4];
    #pragma unroll
    for (int a = 0; a < 2; a++)
        #pragma unroll
        for (int b = 0; b < 8; b++)
            #pragma unroll
            for (int c = 0; c < 4; c++) acc[a][b][c] = 0.f;

    int ch0 = tid, ch1 = tid + 256;
    int ar0 = ch0 >> 2, ac0 = ch0 & 3, ar1 = ch1 >> 2, ac1 = ch1 & 3;
    int wr0 = (ar0 < 64) ? (n0 + ar0) : (448 + n0 + ar0);
    int wr1 = (ar1 < 64) ? (n0 + ar1) : (448 + n0 + ar1);

    int rl = lane & 7, q2 = (lane >> 3) & 1, q1 = lane >> 4;

    // it = slice*2 + sub; sub0: A=yh (+ B load), sub1: A=yl (B reused)
    #define LOADT(it) do {                                                       \
        int it_ = (it);                                                          \
        int k0_ = (it_ >> 1) << 5;                                               \
        const __half* Y_ = (it_ & 1) ? g_yl : g_yh;                              \
        uint32_t Ab_ = sbase + (it_ & 1 ? 10240 : 0);                            \
        cpa16(Ab_ + ar0*80 + ac0*16, Y_ + (size_t)(m0 + ar0)*HH + k0_ + ac0*8);  \
        cpa16(Ab_ + ar1*80 + ac1*16, Y_ + (size_t)(m0 + ar1)*HH + k0_ + ac1*8);  \
        if ((it_ & 1) == 0) {                                                    \
            uint32_t Bb_ = sbase + 20480 + ((it_ >> 1) & 1) * 10240;             \
            cpa16(Bb_ + ar0*80 + ac0*16, Wh + (size_t)wr0*HH + k0_ + ac0*8);     \
            cpa16(Bb_ + ar1*80 + ac1*16, Wh + (size_t)wr1*HH + k0_ + ac1*8);     \
        }                                                                        \
        asm volatile("cp.async.commit_group;");                                  \
    } while (0)

    LOADT(0);
    for (int it = 0; it < 32; it++) {
        if (it + 1 < 32) {
            LOADT(it + 1);
            asm volatile("cp.async.wait_group 1;");
        } else {
            asm volatile("cp.async.wait_group 0;");
        }
        __syncthreads();

        uint32_t Ab = sbase + (it & 1 ? 10240 : 0);
        uint32_t Bb = sbase + 20480 + ((it >> 1) & 1) * 10240;
        #pragma unroll
        for (int ks = 0; ks < 2; ks++) {
            int cb = ks << 1;
            uint32_t a[2][4];
            #pragma unroll
            for (int mf = 0; mf < 2; mf++) {
                int row = (wm << 5) + (mf << 4) + (q2 << 3) + rl;
                uint32_t ad = Ab + row*80 + (cb + q1)*16;
                asm volatile("ldmatrix.sync.aligned.m8n8.x4.shared.b16 {%0,%1,%2,%3}, [%4];"
                             : "=r"(a[mf][0]), "=r"(a[mf][1]), "=r"(a[mf][2]), "=r"(a[mf][3])
                             : "r"(ad));
            }
            #pragma unroll
            for (int q = 0; q < 4; q++) {
                int nrow = (wn << 6) + (q << 4) + (q2 << 3) + rl;
                uint32_t bd = Bb + nrow*80 + (cb + q1)*16;
                uint32_t b0, b1, b2, b3;
                asm volatile("ldmatrix.sync.aligned.m8n8.x4.shared.b16 {%0,%1,%2,%3}, [%4];"
                             : "=r"(b0), "=r"(b1), "=r"(b2), "=r"(b3) : "r"(bd));
                #pragma unroll
                for (int mf = 0; mf < 2; mf++) {
                    asm volatile("mma.sync.aligned.m16n8k16.row.col.f32.f16.f16.f32 "
                        "{%0,%1,%2,%3},{%4,%5,%6,%7},{%8,%9},{%0,%1,%2,%3};"
                        : "+f"(acc[mf][2*q][0]), "+f"(acc[mf][2*q][1]),
                          "+f"(acc[mf][2*q][2]), "+f"(acc[mf][2*q][3])
                        : "r"(a[mf][0]), "r"(a[mf][1]), "r"(a[mf][2]), "r"(a[mf][3]),
                          "r"(b0), "r"(b2));
                    asm volatile("mma.sync.aligned.m16n8k16.row.col.f32.f16.f16.f32 "
                        "{%0,%1,%2,%3},{%4,%5,%6,%7},{%8,%9},{%0,%1,%2,%3};"
                        : "+f"(acc[mf][2*q+1][0]), "+f"(acc[mf][2*q+1][1]),
                          "+f"(acc[mf][2*q+1][2]), "+f"(acc[mf][2*q+1][3])
                        : "r"(a[mf][0]), "r"(a[mf][1]), "r"(a[mf][2]), "r"(a[mf][3]),
                          "r"(b1), "r"(b3));
                }
            }
        }
        __syncthreads();
    }
    #undef LOADT

    // epilogue: z1 warps publish (z1+b1) via smem; z0 warps apply GLU + residual
    float* sb = (float*)smraw;
    const float* bias = out_b + (size_t)layer*1024 + n0;
    if (wn == 1) {
        #pragma unroll
        for (int mf = 0; mf < 2; mf++)
            #pragma unroll
            for (int nf = 0; nf < 8; nf++)
                #pragma unroll
                for (int r = 0; r < 4; r++) {
                    int row = mf*16 + (lane >> 2) + ((r >> 1) << 3);
                    int col = nf*8 + ((lane & 3) << 1) + (r & 1);
                    sb[(wm << 11) + (row << 6) + col] = acc[mf][nf][r] + bias[512 + col];
                }
    }
    __syncthreads();
    if (wn == 0) {
        #pragma unroll
        for (int mf = 0; mf < 2; mf++)
            #pragma unroll
            for (int nf = 0; nf < 8; nf++)
                #pragma unroll
                for (int r = 0; r < 4; r++) {
                    int row = mf*16 + (lane >> 2) + ((r >> 1) << 3);
                    int col = nf*8 + ((lane & 3) << 1) + (r & 1);
                    float z0 = acc[mf][nf][r] + bias[col];
                    float z1 = sb[(wm << 11) + (row << 6) + col];
                    float g  = z0 / (1.0f + expf(-z1));
                    g_h[(size_t)(m0 + wm*32 + row)*HH + n0 + col] += g;
                }
    }
}

// ---------------- decoder -----------------------------------------------------
__global__ void __launch_bounds__(256) k_decoder(const float* __restrict__ dec_w,
                                                 const float* __restrict__ dec_b,
                                                 float* __restrict__ out) {
    int row  = blockIdx.x*8 + (threadIdx.x >> 5);
    int lane = threadIdx.x & 31;
    const float* hr = g_h + (size_t)row*HH;
    float s = 0.f;
    #pragma unroll
    for (int j = 0; j < 16; j++) s = fmaf(hr[lane + 32*j], dec_w[lane + 32*j], s);
    #pragma unroll
    for (int o = 16; o > 0; o >>= 1) s += __shfl_xor_sync(0xffffffffu, s, o);
    if (lane == 0) out[row] = s + dec_b[0];
}

// ---------------- driver ------------------------------------------------------
extern "C" void kernel_launch(void* const* d_in, const int* in_sizes, int n_in,
                              void* d_out, int out_size) {
    const float* x      = (const float*)d_in[0];
    const float* enc_w  = (const float*)d_in[1];
    const float* enc_b  = (const float*)d_in[2];
    const float* log_dt = (const float*)d_in[3];
    const float* A_re   = (const float*)d_in[4];
    const float* A_im   = (const float*)d_in[5];
    const float* C_re   = (const float*)d_in[6];
    const float* C_im   = (const float*)d_in[7];
    const float* D      = (const float*)d_in[8];
    const float* out_w  = (const float*)d_in[9];
    const float* out_b  = (const float*)d_in[10];
    const float* ln_w   = (const float*)d_in[11];
    const float* ln_b   = (const float*)d_in[12];
    const float* dec_w  = (const float*)d_in[13];
    const float* dec_b  = (const float*)d_in[14];
    float* out = (float*)d_out;

    k_params<<<(NLAYERS*HH*NN + 255)/256, 256>>>(log_dt, A_re, A_im, C_re, C_im);
    k_wsplit<<<(NLAYERS*2*HH*HH)/256, 256>>>(out_w);
    k_encoder<<<(BB*LL*HH)/256, 256>>>(x, enc_w, enc_b);

    for (int layer = 0; layer < NLAYERS; layer++) {
        dim3 lgrid(LL/32, BB);
        k_ln_t<<<lgrid, 256>>>(ln_w, ln_b, layer);
        k_scan<<<BB*HH, 256>>>(D, layer);
        dim3 sgrid(LL/32, HH/32, BB);
        k_split<<<sgrid, 256>>>();
        dim3 ggrid(HH/64, (BB*LL)/128);
        k_mma_glu<<<ggrid, 256>>>(out_b, layer);
    }
    k_decoder<<<(BB*LL)/8, 256>>>(dec_w, dec_b, out);
}

// round 7
// speedup vs baseline: 1.7777x; 1.0039x over previous
#include <cuda_runtime.h>
#include <cuda_fp16.h>
#include <cstdint>

#define BB 8
#define LL 4096
#define HH 512
#define NN 16
#define NLAYERS 4

typedef unsigned long long u64;

__device__ __forceinline__ u64 pk2(float lo, float hi) {
    u64 r; asm("mov.b64 %0,{%1,%2};" : "=l"(r) : "f"(lo), "f"(hi)); return r;
}
__device__ __forceinline__ void upk2(u64 v, float& lo, float& hi) {
    asm("mov.b64 {%0,%1},%2;" : "=f"(lo), "=f"(hi) : "l"(v));
}
__device__ __forceinline__ u64 f2fma(u64 a, u64 b, u64 c) {
    u64 d; asm("fma.rn.f32x2 %0,%1,%2,%3;" : "=l"(d) : "l"(a), "l"(b), "l"(c)); return d;
}
__device__ __forceinline__ uint32_t smem_u32(const void* p) {
    uint32_t a;
    asm("{ .reg .u64 t; cvta.to.shared.u64 t, %1; cvt.u32.u64 %0, t; }" : "=r"(a) : "l"(p));
    return a;
}
__device__ __forceinline__ void cpa16(uint32_t dst, const void* src) {
    asm volatile("cp.async.cg.shared.global [%0],[%1],16;" :: "r"(dst), "l"(src));
}

// ---------------- scratch ----------------------------------------------------
__device__ float g_h [BB*LL*HH];
__device__ float g_ut[(size_t)BB*HH*LL];
__device__ float g_yt[(size_t)BB*HH*LL];
__device__ float g_w [NLAYERS*HH*NN*2];
__device__ float g_ct[NLAYERS*2*HH*NN*2];
__device__ __half g_yh[(size_t)BB*LL*HH];
__device__ __half g_yl[(size_t)BB*LL*HH];
__device__ __half g_wh[NLAYERS*2*HH*HH];

// ---------------- SSM parameter precompute ----------------------------------
__global__ void k_params(const float* __restrict__ log_dt, const float* __restrict__ A_re,
                         const float* __restrict__ A_im, const float* __restrict__ C_re,
                         const float* __restrict__ C_im) {
    int idx = blockIdx.x * blockDim.x + threadIdx.x;
    if (idx >= NLAYERS*HH*NN) return;
    int n     = idx % NN;
    int h     = (idx / NN) % HH;
    int layer = idx / (HH*NN);
    float dt  = expf(log_dt[layer*HH + h]);
    float are = A_re[idx];
    float aim = A_im[idx];
    float e   = expf(are*dt);
    float wre = e * cosf(aim*dt);
    float wim = e * sinf(aim*dt);
    g_w[idx*2+0] = wre;
    g_w[idx*2+1] = wim;
    float inv = 1.0f / (are*are + aim*aim);
    float nre = wre - 1.0f, nim = wim;
    float fre = (nre*are + nim*aim) * inv;
    float fim = (nim*are - nre*aim) * inv;
    #pragma unroll
    for (int c = 0; c < 2; c++) {
        int cidx = ((layer*2 + c)*HH + h)*NN + n;
        float cre = C_re[cidx], cim = C_im[cidx];
        g_ct[cidx*2+0] = 2.0f*(cre*fre - cim*fim);
        g_ct[cidx*2+1] = 2.0f*(cre*fim + cim*fre);
    }
}

// ---------------- W -> fp16 --------------------------------------------------
__global__ void k_wsplit(const float* __restrict__ out_w) {
    int idx = blockIdx.x * blockDim.x + threadIdx.x;
    g_wh[idx] = __float2half(out_w[idx]);
}

// ---------------- encoder ----------------------------------------------------
__global__ void k_encoder(const float* __restrict__ x, const float* __restrict__ enc_w,
                          const float* __restrict__ enc_b) {
    int idx = blockIdx.x * blockDim.x + threadIdx.x;
    int hh = idx % HH;
    int l  = (idx / HH) % LL;
    int b  = idx / (LL*HH);
    float grid = (float)l * (1.0f/(LL-1));
    g_h[idx] = enc_w[hh*2+0]*x[b*LL + l] + enc_w[hh*2+1]*grid + enc_b[hh];
}

// ---------------- LayerNorm + transpose to (B,H,L) ---------------------------
__global__ void __launch_bounds__(256) k_ln_t(const float* __restrict__ ln_w,
                                              const float* __restrict__ ln_b, int layer) {
    __shared__ float s_mean[32], s_rstd[32];
    __shared__ float tile[64][33];
    int b  = blockIdx.y;
    int l0 = blockIdx.x * 32;
    int tid = threadIdx.x, warp = tid >> 5, lane = tid & 31;
    const float* lw = ln_w + layer*HH;
    const float* lb = ln_b + layer*HH;

    for (int r = warp; r < 32; r += 8) {
        const float* row = g_h + ((size_t)b*LL + l0 + r)*HH;
        float sum = 0.f, sq = 0.f;
        #pragma unroll
        for (int j = 0; j < 16; j++) { float v = row[lane + 32*j]; sum += v; sq += v*v; }
        #pragma unroll
        for (int o = 16; o > 0; o >>= 1) {
            sum += __shfl_xor_sync(0xffffffffu, sum, o);
            sq  += __shfl_xor_sync(0xffffffffu, sq , o);
        }
        if (lane == 0) {
            float mu = sum * (1.0f/HH);
            s_mean[r] = mu;
            s_rstd[r] = rsqrtf(sq * (1.0f/HH) - mu*mu + 1e-5f);
        }
    }
    __syncthreads();

    for (int h0 = 0; h0 < HH; h0 += 64) {
        #pragma unroll
        for (int p = 0; p < 8; p++) {
            int r = p*4 + (tid >> 6);
            int c = tid & 63;
            float v = g_h[((size_t)b*LL + l0 + r)*HH + h0 + c];
            tile[c][r] = (v - s_mean[r]) * s_rstd[r] * lw[h0 + c] + lb[h0 + c];
        }
        __syncthreads();
        #pragma unroll
        for (int p = 0; p < 8; p++) {
            int hh = p*8 + (tid >> 5);
            int lc = tid & 31;
            g_ut[((size_t)b*HH + h0 + hh)*LL + l0 + lc] = tile[hh][lc];
        }
        __syncthreads();
    }
}

// ---------------- bidirectional SSM scan: 8 modes/thread ---------------------
// 256 threads = 64 chunks(64 steps) x 2 dirs x 2 n-threads (8 n each, 4 pairs).
__global__ void __launch_bounds__(256) k_scan(const float* __restrict__ Din, int layer) {
    __shared__ float su[4161];                  // skewed: idx = t + (t>>6)
    __shared__ __align__(8) char uni[16648];    // union: chunk-state (16KB) / sy
    u64*   st = (u64*)uni;
    float* sy = (float*)uni;

    int bh = blockIdx.x;
    int h  = bh & 511;
    int tid = threadIdx.x;
    const float* urow = g_ut + (size_t)bh * LL;

    for (int t = tid; t < 4096; t += 256) su[t + (t >> 6)] = urow[t];
    if (tid == 0) su[4160] = 0.0f;              // u[4096] = 0 pad
    __syncthreads();

    int n2    = tid & 1;                        // owns pairs P = 4*n2 + j'
    int dir   = (tid >> 1) & 1;
    int chunk = tid >> 2;                       // 0..63
    int t0    = chunk << 6;

    const float* wb = g_w  + (size_t)(layer*HH + h)*NN*2;
    const float* cb = g_ct + (size_t)((layer*2 + dir)*HH + h)*NN*2;
    u64 wre2[4], wim2[4], nwim2[4], cre2[4], ncim2[4];
    #pragma unroll
    for (int j = 0; j < 4; j++) {
        int base = (4*n2 + j) * 4;              // pair P = 4*n2+j holds n = 2P, 2P+1
        float r0 = wb[base],   i0 = wb[base+1];
        float r1 = wb[base+2], i1 = wb[base+3];
        wre2[j]  = pk2(r0, r1);
        wim2[j]  = pk2(i0, i1);
        nwim2[j] = pk2(-i0, -i1);
        cre2[j]  = pk2(cb[base], cb[base+2]);
        ncim2[j] = pk2(-cb[base+1], -cb[base+3]);
    }
    const u64 ZERO = 0ULL;

    // pass 1: chunk-local sums from zero state
    u64 sre[4] = {0,0,0,0}, sim[4] = {0,0,0,0};
    #pragma unroll 4
    for (int i = 0; i < 64; i++) {
        int t = dir ? (t0 + 64 - i) : (t0 + i);
        float u = su[t + (t >> 6)];
        u64 u2 = pk2(u, u);
        #pragma unroll
        for (int j = 0; j < 4; j++) {
            u64 tre = f2fma(wre2[j], sre[j], u2);
            tre     = f2fma(nwim2[j], sim[j], tre);
            u64 tim = f2fma(wim2[j], sre[j], ZERO);
            tim     = f2fma(wre2[j], sim[j], tim);
            sre[j] = tre; sim[j] = tim;
        }
    }
    {
        int s = ((dir*64 + chunk)*8 + 4*n2)*2;
        #pragma unroll
        for (int j = 0; j < 4; j++) { st[s + 2*j] = sre[j]; st[s + 2*j + 1] = sim[j]; }
    }
    __syncthreads();

    // combine: 16 threads, each one (dir, pair); in-place sums -> carries
    if (tid < 16) {
        int d = tid >> 3, P = tid & 7;
        int base = 4*P;
        float ra = wb[base], ia = wb[base+1], rb = wb[base+2], ib = wb[base+3];
        #pragma unroll
        for (int q = 0; q < 6; q++) {           // w^64
            float t1 = ra*ra - ia*ia; ia = 2.0f*ra*ia; ra = t1;
            float t2 = rb*rb - ib*ib; ib = 2.0f*rb*ib; rb = t2;
        }
        u64 Pre = pk2(ra, rb), Pim = pk2(ia, ib), nPim = pk2(-ia, -ib);
        u64 Fre = 0ULL, Fim = 0ULL;
        if (d == 0) {
            for (int c = 0; c < 64; c++) {
                int s = (c*8 + P)*2;
                u64 Sre = st[s], Sim = st[s+1];
                st[s] = Fre; st[s+1] = Fim;
                u64 t1 = f2fma(Pre, Fre, Sre);
                u64 nFre = f2fma(nPim, Fim, t1);
                u64 t2 = f2fma(Pre, Fim, Sim);
                u64 nFim = f2fma(Pim, Fre, t2);
                Fre = nFre; Fim = nFim;
            }
        } else {
            for (int c = 63; c >= 0; c--) {
                int s = ((64 + c)*8 + P)*2;
                u64 Sre = st[s], Sim = st[s+1];
                st[s] = Fre; st[s+1] = Fim;
                u64 t1 = f2fma(Pre, Fre, Sre);
                u64 nFre = f2fma(nPim, Fim, t1);
                u64 t2 = f2fma(Pre, Fim, Sim);
                u64 nFim = f2fma(Pim, Fre, t2);
                Fre = nFre; Fim = nFim;
            }
        }
    }
    __syncthreads();

    // load carries, then barrier before sy overwrites the union
    {
        int s = ((dir*64 + chunk)*8 + 4*n2)*2;
        #pragma unroll
        for (int j = 0; j < 4; j++) { sre[j] = st[s + 2*j]; sim[j] = st[s + 2*j + 1]; }
    }
    __syncthreads();

    // pass 2: full scan; emit with D*u folded at first touch
    float Dh = Din[layer*HH + h];
    #pragma unroll 4
    for (int i = 0; i < 64; i++) {
        int tout = dir ? (t0 + 63 - i) : (t0 + i);
        int tu   = tout + dir;                  // bwd consumes u[t+1]
        float u  = su[tu + (tu >> 6)];
        u64 u2 = pk2(u, u);
        u64 v2 = 0ULL;
        #pragma unroll
        for (int j = 0; j < 4; j++) {
            u64 tre = f2fma(wre2[j], sre[j], u2);
            tre     = f2fma(nwim2[j], sim[j], tre);
            u64 tim = f2fma(wim2[j], sre[j], ZERO);
            tim     = f2fma(wre2[j], sim[j], tim);
            sre[j] = tre; sim[j] = tim;
            v2 = f2fma(cre2[j], tre, v2);
            v2 = f2fma(ncim2[j], tim, v2);
        }
        float va, vb; upk2(v2, va, vb);
        float v = va + vb;
        v += __shfl_xor_sync(0xffffffffu, v, 1);    // partner n2
        if (n2 == 0) {
            int ts = tout + (tout >> 6);
            // first toucher of sy[t] is whichever dir has i < 32 for this t
            if (i < 32) sy[ts] = fmaf(Dh, su[ts], v);
            else        sy[ts] += v;
        }
    }
    __syncthreads();

    // epilogue: exact-erf GELU, write (B,H,L)
    float* orow = g_yt + (size_t)bh * LL;
    for (int t = tid; t < 4096; t += 256) {
        float v = sy[t + (t >> 6)];
        orow[t] = 0.5f * v * (1.0f + erff(v * 0.70710678118f));
    }
}

// ---------------- transpose + fp16 hi/lo split: (B,H,L) -> (B,L,H) -----------
__global__ void __launch_bounds__(256) k_split() {
    __shared__ float t[32][33];
    int b  = blockIdx.z;
    int h0 = blockIdx.y * 32;
    int l0 = blockIdx.x * 32;
    int tid = threadIdx.x, lane = tid & 31, r = tid >> 5;
    #pragma unroll
    for (int q = 0; q < 4; q++) {
        int hh = r + 8*q;
        t[hh][lane] = g_yt[((size_t)(b*HH + h0 + hh))*LL + l0 + lane];
    }
    __syncthreads();
    #pragma unroll
    for (int q = 0; q < 4; q++) {
        int ll = r + 8*q;
        float v = t[lane][ll];
        __half hi = __float2half(v);
        size_t o = ((size_t)(b*LL + l0 + ll))*HH + h0 + lane;
        g_yh[o] = hi;
        g_yl[o] = __float2half(v - __half2float(hi));
    }
}

// ---------------- fp16 HMMA GEMM (2-term split) + GLU + residual -------------
// CTA tile 128m x 128n (64 z0-cols + paired 64 z1-cols), 16 k-slices x 2 passes.
// B (weights) loaded once per k-slice, reused by both A passes (yh, yl).
__global__ void __launch_bounds__(256) k_mma_glu(const float* __restrict__ out_b, int layer) {
    __shared__ alignas(16) char smraw[40960];   // A: 2 x 10240 | B: 2 x 10240
    int tid = threadIdx.x, warp = tid >> 5, lane = tid & 31;
    int wm = warp & 3, wn = warp >> 2;
    int n0 = blockIdx.x * 64;
    int m0 = blockIdx.y * 128;
    uint32_t sbase = smem_u32(smraw);

    const __half* Wh = g_wh + (size_t)layer*2*HH*HH;

    float acc[2][8][4];
    #pragma unroll
    for (int a = 0; a < 2; a++)
        #pragma unroll
        for (int b = 0; b < 8; b++)
            #pragma unroll
            for (int c = 0; c < 4; c++) acc[a][b][c] = 0.f;

    int ch0 = tid, ch1 = tid + 256;
    int ar0 = ch0 >> 2, ac0 = ch0 & 3, ar1 = ch1 >> 2, ac1 = ch1 & 3;
    int wr0 = (ar0 < 64) ? (n0 + ar0) : (448 + n0 + ar0);
    int wr1 = (ar1 < 64) ? (n0 + ar1) : (448 + n0 + ar1);

    int rl = lane & 7, q2 = (lane >> 3) & 1, q1 = lane >> 4;

    // it = slice*2 + sub; sub0: A=yh (+ B load), sub1: A=yl (B reused)
    #define LOADT(it) do {                                                       \
        int it_ = (it);                                                          \
        int k0_ = (it_ >> 1) << 5;                                               \
        const __half* Y_ = (it_ & 1) ? g_yl : g_yh;                              \
        uint32_t Ab_ = sbase + (it_ & 1 ? 10240 : 0);                            \
        cpa16(Ab_ + ar0*80 + ac0*16, Y_ + (size_t)(m0 + ar0)*HH + k0_ + ac0*8);  \
        cpa16(Ab_ + ar1*80 + ac1*16, Y_ + (size_t)(m0 + ar1)*HH + k0_ + ac1*8);  \
        if ((it_ & 1) == 0) {                                                    \
            uint32_t Bb_ = sbase + 20480 + ((it_ >> 1) & 1) * 10240;             \
            cpa16(Bb_ + ar0*80 + ac0*16, Wh + (size_t)wr0*HH + k0_ + ac0*8);     \
            cpa16(Bb_ + ar1*80 + ac1*16, Wh + (size_t)wr1*HH + k0_ + ac1*8);     \
        }                                                                        \
        asm volatile("cp.async.commit_group;");                                  \
    } while (0)

    LOADT(0);
    for (int it = 0; it < 32; it++) {
        if (it + 1 < 32) {
            LOADT(it + 1);
            asm volatile("cp.async.wait_group 1;");
        } else {
            asm volatile("cp.async.wait_group 0;");
        }
        __syncthreads();

        uint32_t Ab = sbase + (it & 1 ? 10240 : 0);
        uint32_t Bb = sbase + 20480 + ((it >> 1) & 1) * 10240;
        #pragma unroll
        for (int ks = 0; ks < 2; ks++) {
            int cb = ks << 1;
            uint32_t a[2][4];
            #pragma unroll
            for (int mf = 0; mf < 2; mf++) {
                int row = (wm << 5) + (mf << 4) + (q2 << 3) + rl;
                uint32_t ad = Ab + row*80 + (cb + q1)*16;
                asm volatile("ldmatrix.sync.aligned.m8n8.x4.shared.b16 {%0,%1,%2,%3}, [%4];"
                             : "=r"(a[mf][0]), "=r"(a[mf][1]), "=r"(a[mf][2]), "=r"(a[mf][3])
                             : "r"(ad));
            }
            #pragma unroll
            for (int q = 0; q < 4; q++) {
                int nrow = (wn << 6) + (q << 4) + (q2 << 3) + rl;
                uint32_t bd = Bb + nrow*80 + (cb + q1)*16;
                uint32_t b0, b1, b2, b3;
                asm volatile("ldmatrix.sync.aligned.m8n8.x4.shared.b16 {%0,%1,%2,%3}, [%4];"
                             : "=r"(b0), "=r"(b1), "=r"(b2), "=r"(b3) : "r"(bd));
                #pragma unroll
                for (int mf = 0; mf < 2; mf++) {
                    asm volatile("mma.sync.aligned.m16n8k16.row.col.f32.f16.f16.f32 "
                        "{%0,%1,%2,%3},{%4,%5,%6,%7},{%8,%9},{%0,%1,%2,%3};"
                        : "+f"(acc[mf][2*q][0]), "+f"(acc[mf][2*q][1]),
                          "+f"(acc[mf][2*q][2]), "+f"(acc[mf][2*q][3])
                        : "r"(a[mf][0]), "r"(a[mf][1]), "r"(a[mf][2]), "r"(a[mf][3]),
                          "r"(b0), "r"(b2));
                    asm volatile("mma.sync.aligned.m16n8k16.row.col.f32.f16.f16.f32 "
                        "{%0,%1,%2,%3},{%4,%5,%6,%7},{%8,%9},{%0,%1,%2,%3};"
                        : "+f"(acc[mf][2*q+1][0]), "+f"(acc[mf][2*q+1][1]),
                          "+f"(acc[mf][2*q+1][2]), "+f"(acc[mf][2*q+1][3])
                        : "r"(a[mf][0]), "r"(a[mf][1]), "r"(a[mf][2]), "r"(a[mf][3]),
                          "r"(b1), "r"(b3));
                }
            }
        }
        __syncthreads();
    }
    #undef LOADT

    // epilogue: z1 warps publish (z1+b1) via smem; z0 warps apply GLU + residual
    float* sb = (float*)smraw;
    const float* bias = out_b + (size_t)layer*1024 + n0;
    if (wn == 1) {
        #pragma unroll
        for (int mf = 0; mf < 2; mf++)
            #pragma unroll
            for (int nf = 0; nf < 8; nf++)
                #pragma unroll
                for (int r = 0; r < 4; r++) {
                    int row = mf*16 + (lane >> 2) + ((r >> 1) << 3);
                    int col = nf*8 + ((lane & 3) << 1) + (r & 1);
                    sb[(wm << 11) + (row << 6) + col] = acc[mf][nf][r] + bias[512 + col];
                }
    }
    __syncthreads();
    if (wn == 0) {
        #pragma unroll
        for (int mf = 0; mf < 2; mf++)
            #pragma unroll
            for (int nf = 0; nf < 8; nf++)
                #pragma unroll
                for (int r = 0; r < 4; r++) {
                    int row = mf*16 + (lane >> 2) + ((r >> 1) << 3);
                    int col = nf*8 + ((lane & 3) << 1) + (r & 1);
                    float z0 = acc[mf][nf][r] + bias[col];
                    float z1 = sb[(wm << 11) + (row << 6) + col];
                    float g  = z0 / (1.0f + expf(-z1));
                    g_h[(size_t)(m0 + wm*32 + row)*HH + n0 + col] += g;
                }
    }
}

// ---------------- decoder -----------------------------------------------------
__global__ void __launch_bounds__(256) k_decoder(const float* __restrict__ dec_w,
                                                 const float* __restrict__ dec_b,
                                                 float* __restrict__ out) {
    int row  = blockIdx.x*8 + (threadIdx.x >> 5);
    int lane = threadIdx.x & 31;
    const float* hr = g_h + (size_t)row*HH;
    float s = 0.f;
    #pragma unroll
    for (int j = 0; j < 16; j++) s = fmaf(hr[lane + 32*j], dec_w[lane + 32*j], s);
    #pragma unroll
    for (int o = 16; o > 0; o >>= 1) s += __shfl_xor_sync(0xffffffffu, s, o);
    if (lane == 0) out[row] = s + dec_b[0];
}

// ---------------- driver ------------------------------------------------------
extern "C" void kernel_launch(void* const* d_in, const int* in_sizes, int n_in,
                              void* d_out, int out_size) {
    const float* x      = (const float*)d_in[0];
    const float* enc_w  = (const float*)d_in[1];
    const float* enc_b  = (const float*)d_in[2];
    const float* log_dt = (const float*)d_in[3];
    const float* A_re   = (const float*)d_in[4];
    const float* A_im   = (const float*)d_in[5];
    const float* C_re   = (const float*)d_in[6];
    const float* C_im   = (const float*)d_in[7];
    const float* D      = (const float*)d_in[8];
    const float* out_w  = (const float*)d_in[9];
    const float* out_b  = (const float*)d_in[10];
    const float* ln_w   = (const float*)d_in[11];
    const float* ln_b   = (const float*)d_in[12];
    const float* dec_w  = (const float*)d_in[13];
    const float* dec_b  = (const float*)d_in[14];
    float* out = (float*)d_out;

    k_params<<<(NLAYERS*HH*NN + 255)/256, 256>>>(log_dt, A_re, A_im, C_re, C_im);
    k_wsplit<<<(NLAYERS*2*HH*HH)/256, 256>>>(out_w);
    k_encoder<<<(BB*LL*HH)/256, 256>>>(x, enc_w, enc_b);

    for (int layer = 0; layer < NLAYERS; layer++) {
        dim3 lgrid(LL/32, BB);
        k_ln_t<<<lgrid, 256>>>(ln_w, ln_b, layer);
        k_scan<<<BB*HH, 256>>>(D, layer);
        dim3 sgrid(LL/32, HH/32, BB);
        k_split<<<sgrid, 256>>>();
        dim3 ggrid(HH/64, (BB*LL)/128);
        k_mma_glu<<<ggrid, 256>>>(out_b, layer);
    }
    k_decoder<<<(BB*LL)/8, 256>>>(dec_w, dec_b, out);
}